// round 8
// baseline (speedup 1.0000x reference)
#include <cuda_runtime.h>
#include <math.h>
#include <stdint.h>

// ---------------------------------------------------------------------------
// Problem: D=512, H=8 (e=64), B=64 studies, N=131072 cells.
// Padded layout: row r = n*64 + g. max_n data-dependent; CAP upper bound.
// All GEMM operands tf32-rounded AT THE PRODUCER -> raw fp32 bits into
// mma.sync (HW truncation is identity on pre-rounded values).
// ---------------------------------------------------------------------------
#define CAP       2560
#define ROWS_CAP  (CAP * 64)   // 163840

__device__ int g_maxn;
__device__ int g_starts[65];
__device__ int g_counts[64];

__device__ float g_X  [(size_t)ROWS_CAP * 512];
__device__ float g_QKV[(size_t)ROWS_CAP * 1536];
__device__ float g_ATT[(size_t)ROWS_CAP * 512];
__device__ float g_TMP[(size_t)ROWS_CAP * 512];
__device__ float g_HID[(size_t)ROWS_CAP * 1024];
__device__ float g_Wr [2097152];   // rounded W_in | W_o | W1 | W2

__device__ __forceinline__ uint32_t f2tf32(float f) {
    uint32_t r;
    asm("cvt.rna.tf32.f32 %0, %1;" : "=r"(r) : "f"(f));
    return r;
}
__device__ __forceinline__ float rnd_tf32(float f) {
    return __uint_as_float(f2tf32(f));
}

// ---------------------------------------------------------------------------
// Meta / zeropad / scatter / weight rounding
// ---------------------------------------------------------------------------
__global__ void k_meta(const int* __restrict__ idx, int N) {
    __shared__ int st[65];
    __shared__ int smax;
    int t = threadIdx.x;
    if (t == 0) smax = 0;
    if (t <= 64) {
        if (t == 64) st[64] = N;
        else {
            int lo = 0, hi = N;
            while (lo < hi) { int mid = (lo + hi) >> 1; if (idx[mid] < t) lo = mid + 1; else hi = mid; }
            st[t] = lo;
        }
    }
    __syncthreads();
    if (t < 64) {
        int c = st[t + 1] - st[t];
        g_starts[t] = st[t];
        g_counts[t] = c;
        atomicMax(&smax, c);
    }
    if (t == 64) g_starts[64] = N;
    __syncthreads();
    if (t == 0) g_maxn = (smax < CAP) ? smax : CAP;
}

__global__ void k_zeropad() {
    int g = blockIdx.x;
    int c0 = g_counts[g];
    int rows = g_maxn - c0;
    if (rows <= 0) return;
    float4 z = make_float4(0.f, 0.f, 0.f, 0.f);
    for (int w = threadIdx.x; w < rows * 128; w += 256) {
        int n = c0 + (w >> 7);
        int j = w & 127;
        ((float4*)(g_X + (size_t)((n << 6) + g) * 512))[j] = z;
    }
}

__global__ void k_scatter(const float* __restrict__ emb, const int* __restrict__ idx) {
    int i = blockIdx.x;
    int g = idx[i];
    int n = i - g_starts[g];
    float4 v = ((const float4*)(emb + (size_t)i * 512))[threadIdx.x];
    v.x = rnd_tf32(v.x); v.y = rnd_tf32(v.y); v.z = rnd_tf32(v.z); v.w = rnd_tf32(v.w);
    ((float4*)(g_X + (size_t)(n * 64 + g) * 512))[threadIdx.x] = v;
}

__global__ void k_roundw(const float* __restrict__ s, float* __restrict__ d, int n4) {
    int i = blockIdx.x * 256 + threadIdx.x;
    if (i >= n4) return;
    float4 v = ((const float4*)s)[i];
    v.x = rnd_tf32(v.x); v.y = rnd_tf32(v.y); v.z = rnd_tf32(v.z); v.w = rnd_tf32(v.w);
    ((float4*)d)[i] = v;
}

// ---------------------------------------------------------------------------
// tf32 tensor-core GEMM, low-smem-redundancy variant:
// BM=128, BN=256, BK=32. 8 warps (2x4), warp tile 64x64 (4x8 m16n8k8).
// 3-stage cp.async ring, ldmatrix x4 frags, register double-buffer over kk.
// 1 CTA/SM (8 warps) -- smem-read demand per tensor-cycle drops 2.0 -> 1.34.
// ---------------------------------------------------------------------------
#define SROW 36
#define A_W   (128 * SROW)              // 4608 words
#define B_W   (256 * SROW)              // 9216 words
#define STAGE_B ((A_W + B_W) * 4u)      // 55296 bytes
#define TG_SMEM_BYTES (3u * STAGE_B)    // 165888

__device__ __forceinline__ void mma_tf32(float c[4],
                                         uint32_t a0, uint32_t a1, uint32_t a2, uint32_t a3,
                                         uint32_t b0, uint32_t b1) {
    asm volatile(
        "mma.sync.aligned.m16n8k8.row.col.f32.tf32.tf32.f32 "
        "{%0,%1,%2,%3}, {%4,%5,%6,%7}, {%8,%9}, {%0,%1,%2,%3};"
        : "+f"(c[0]), "+f"(c[1]), "+f"(c[2]), "+f"(c[3])
        : "r"(a0), "r"(a1), "r"(a2), "r"(a3), "r"(b0), "r"(b1));
}
#define LDSM4(f, a) \
    asm volatile("ldmatrix.sync.aligned.m8n8.x4.shared.b16 {%0,%1,%2,%3}, [%4];" \
                 : "=r"((f)[0]), "=r"((f)[1]), "=r"((f)[2]), "=r"((f)[3]) : "r"(a))

__global__ __launch_bounds__(256, 1)
void k_tgemm(const float* __restrict__ A, const float* __restrict__ Bw,
             const float* __restrict__ bias, const float* __restrict__ resid,
             float* __restrict__ C, int Ncols, int K, int relu, int round_out)
{
    int M = g_maxn * 64;
    int row0 = blockIdx.y * 128;
    if (row0 >= M) return;
    int col0 = blockIdx.x * 256;

    int tid  = threadIdx.x;
    int lane = tid & 31;
    int wid  = tid >> 5;
    int wm   = wid & 1;        // 2 warp rows x 64
    int wn   = wid >> 1;       // 4 warp cols x 64
    int g    = lane >> 2;
    int tg   = lane & 3;

    extern __shared__ uint32_t sm[];
    uint32_t smb = (uint32_t)__cvta_generic_to_shared(sm);

    const float* Abase = A  + (size_t)row0 * K;
    const float* Bbase = Bw + (size_t)col0 * K;

    int srow = tid >> 3;       // 0..31
    int sc4  = tid & 7;

    // LDSM lane byte offsets
    uint32_t rowA = (uint32_t)(((wm * 64 + (lane & 15)) * SROW + (lane >> 4) * 4) * 4);
    uint32_t rowB = (uint32_t)(((wn * 64 + (lane & 7) + (lane >> 4) * 8) * SROW
                                + ((lane >> 3) & 1) * 4) * 4);

    float c[4][8][4];
#pragma unroll
    for (int i = 0; i < 4; i++)
#pragma unroll
        for (int j = 0; j < 8; j++)
#pragma unroll
            for (int k = 0; k < 4; k++) c[i][j][k] = 0.f;

    const int KT = K >> 5;

#define STAGE(kt_)  do {                                                          \
        int _kt = (kt_);                                                          \
        uint32_t _sb = smb + (uint32_t)(_kt % 3) * STAGE_B;                       \
        int _ko = _kt * 32 + sc4 * 4;                                             \
        _Pragma("unroll")                                                         \
        for (int _i = 0; _i < 4; _i++) {                                          \
            int _row = srow + 32 * _i;                                            \
            uint32_t _d = _sb + (uint32_t)((_row * SROW + sc4 * 4) * 4);          \
            int _ok = (row0 + _row) < M;                                          \
            const float* _sa = Abase + (size_t)(_ok ? _row : 0) * K + _ko;        \
            int _sz = _ok ? 16 : 0;                                               \
            asm volatile("cp.async.cg.shared.global [%0], [%1], 16, %2;"          \
                         :: "r"(_d), "l"(_sa), "r"(_sz));                         \
        }                                                                         \
        _Pragma("unroll")                                                         \
        for (int _i = 0; _i < 8; _i++) {                                          \
            int _row = srow + 32 * _i;                                            \
            uint32_t _d = _sb + (uint32_t)(A_W * 4)                               \
                        + (uint32_t)((_row * SROW + sc4 * 4) * 4);                \
            const float* _sb2 = Bbase + (size_t)_row * K + _ko;                   \
            asm volatile("cp.async.cg.shared.global [%0], [%1], 16;"              \
                         :: "r"(_d), "l"(_sb2));                                  \
        }                                                                         \
        asm volatile("cp.async.commit_group;");                                   \
    } while (0)

    STAGE(0);
    STAGE(1);

    uint32_t fa[2][4][4], fb[2][4][4];

    for (int kt = 0; kt < KT; kt++) {
        if (kt + 1 < KT) { asm volatile("cp.async.wait_group 1;"); }
        else             { asm volatile("cp.async.wait_group 0;"); }
        __syncthreads();
        if (kt + 2 < KT) STAGE(kt + 2);   // overwrites buffer consumed at kt-1

        uint32_t aB = smb + (uint32_t)(kt % 3) * STAGE_B + rowA;
        uint32_t bB = smb + (uint32_t)(kt % 3) * STAGE_B + (uint32_t)(A_W * 4) + rowB;

        // fragments for kk=0
#pragma unroll
        for (int mt = 0; mt < 4; mt++)
            LDSM4(fa[0][mt], aB + (uint32_t)(mt * 16 * SROW * 4));
#pragma unroll
        for (int p = 0; p < 4; p++)
            LDSM4(fb[0][p], bB + (uint32_t)(p * 16 * SROW * 4));

#pragma unroll
        for (int kk = 0; kk < 4; kk++) {
            const int cb = kk & 1, nb = cb ^ 1;
            if (kk < 3) {
#pragma unroll
                for (int mt = 0; mt < 4; mt++)
                    LDSM4(fa[nb][mt], aB + (uint32_t)((mt * 16 * SROW + (kk + 1) * 8) * 4));
#pragma unroll
                for (int p = 0; p < 4; p++)
                    LDSM4(fb[nb][p], bB + (uint32_t)((p * 16 * SROW + (kk + 1) * 8) * 4));
            }
#pragma unroll
            for (int p = 0; p < 4; p++)
#pragma unroll
                for (int mt = 0; mt < 4; mt++) {
                    mma_tf32(c[mt][2 * p],
                             fa[cb][mt][0], fa[cb][mt][1], fa[cb][mt][2], fa[cb][mt][3],
                             fb[cb][p][0], fb[cb][p][1]);
                    mma_tf32(c[mt][2 * p + 1],
                             fa[cb][mt][0], fa[cb][mt][1], fa[cb][mt][2], fa[cb][mt][3],
                             fb[cb][p][2], fb[cb][p][3]);
                }
        }
    }

    // epilogue: bias (+resid) (relu) (tf32 round if output feeds a GEMM)
#pragma unroll
    for (int mt = 0; mt < 4; mt++) {
        int r0 = row0 + wm * 64 + mt * 16 + g;
        int r1 = r0 + 8;
#pragma unroll
        for (int nt = 0; nt < 8; nt++) {
            int cc = col0 + wn * 64 + nt * 8 + 2 * tg;
            float2 bv = *(const float2*)(bias + cc);
            if (r0 < M) {
                float2 o = make_float2(c[mt][nt][0] + bv.x, c[mt][nt][1] + bv.y);
                if (resid) {
                    float2 rv = *(const float2*)(resid + (size_t)r0 * Ncols + cc);
                    o.x += rv.x; o.y += rv.y;
                }
                if (relu) { o.x = fmaxf(o.x, 0.f); o.y = fmaxf(o.y, 0.f); }
                if (round_out) { o.x = rnd_tf32(o.x); o.y = rnd_tf32(o.y); }
                *(float2*)(C + (size_t)r0 * Ncols + cc) = o;
            }
            if (r1 < M) {
                float2 o = make_float2(c[mt][nt][2] + bv.x, c[mt][nt][3] + bv.y);
                if (resid) {
                    float2 rv = *(const float2*)(resid + (size_t)r1 * Ncols + cc);
                    o.x += rv.x; o.y += rv.y;
                }
                if (relu) { o.x = fmaxf(o.x, 0.f); o.y = fmaxf(o.y, 0.f); }
                if (round_out) { o.x = rnd_tf32(o.x); o.y = rnd_tf32(o.y); }
                *(float2*)(C + (size_t)r1 * Ncols + cc) = o;
            }
        }
    }
#undef STAGE
}

// ---------------------------------------------------------------------------
// Attention: one block per (position n, head h). Output tf32-rounded.
// ---------------------------------------------------------------------------
__global__ __launch_bounds__(256)
void k_attn(const float* __restrict__ QKV, float* __restrict__ ATT) {
    int n = blockIdx.x;
    if (n >= g_maxn) return;
    int h = blockIdx.y;

    __shared__ float Qt[64][64];
    __shared__ float Kt[64][64];
    __shared__ float V [64][64];

    int tid = threadIdx.x;
    size_t base = (size_t)n * 64 * 1536 + (size_t)h * 64;
    for (int idx = tid; idx < 4096; idx += 256) {
        int s = idx >> 6, e = idx & 63;
        size_t rb = base + (size_t)s * 1536 + e;
        Qt[e][s] = QKV[rb];
        Kt[e][s] = QKV[rb + 512];
        V [s][e] = QKV[rb + 1024];
    }
    __syncthreads();

    int s  = tid >> 2;
    int qd = tid & 3;
    int t0 = qd << 4;

    float acc[16];
#pragma unroll
    for (int j = 0; j < 16; j++) acc[j] = 0.f;

#pragma unroll 4
    for (int e = 0; e < 64; e++) {
        float  qv = Qt[e][s];
        float4 k0 = *(const float4*)&Kt[e][t0 + 0];
        float4 k1 = *(const float4*)&Kt[e][t0 + 4];
        float4 k2 = *(const float4*)&Kt[e][t0 + 8];
        float4 k3 = *(const float4*)&Kt[e][t0 + 12];
        acc[0]  = fmaf(qv, k0.x, acc[0]);  acc[1]  = fmaf(qv, k0.y, acc[1]);
        acc[2]  = fmaf(qv, k0.z, acc[2]);  acc[3]  = fmaf(qv, k0.w, acc[3]);
        acc[4]  = fmaf(qv, k1.x, acc[4]);  acc[5]  = fmaf(qv, k1.y, acc[5]);
        acc[6]  = fmaf(qv, k1.z, acc[6]);  acc[7]  = fmaf(qv, k1.w, acc[7]);
        acc[8]  = fmaf(qv, k2.x, acc[8]);  acc[9]  = fmaf(qv, k2.y, acc[9]);
        acc[10] = fmaf(qv, k2.z, acc[10]); acc[11] = fmaf(qv, k2.w, acc[11]);
        acc[12] = fmaf(qv, k3.x, acc[12]); acc[13] = fmaf(qv, k3.y, acc[13]);
        acc[14] = fmaf(qv, k3.z, acc[14]); acc[15] = fmaf(qv, k3.w, acc[15]);
    }

    float mx = -1e30f;
#pragma unroll
    for (int j = 0; j < 16; j++) {
        float v = acc[j] * 0.125f;
        if (g_counts[t0 + j] <= n) v = -1e30f;
        acc[j] = v;
        mx = fmaxf(mx, v);
    }
    mx = fmaxf(mx, __shfl_xor_sync(0xffffffffu, mx, 1, 4));
    mx = fmaxf(mx, __shfl_xor_sync(0xffffffffu, mx, 2, 4));
    float sum = 0.f;
#pragma unroll
    for (int j = 0; j < 16; j++) { float p = __expf(acc[j] - mx); acc[j] = p; sum += p; }
    sum += __shfl_xor_sync(0xffffffffu, sum, 1, 4);
    sum += __shfl_xor_sync(0xffffffffu, sum, 2, 4);
    float inv = 1.f / sum;
#pragma unroll
    for (int j = 0; j < 16; j++) acc[j] *= inv;

    float o[16];
#pragma unroll
    for (int j = 0; j < 16; j++) o[j] = 0.f;
    int e0 = qd << 4;
#pragma unroll
    for (int tq = 0; tq < 4; tq++) {
#pragma unroll
        for (int j2 = 0; j2 < 16; j2++) {
            float a = __shfl_sync(0xffffffffu, acc[j2], tq, 4);
            const float* vr = &V[tq * 16 + j2][e0];
            float4 v0 = *(const float4*)(vr + 0);
            float4 v1 = *(const float4*)(vr + 4);
            float4 v2 = *(const float4*)(vr + 8);
            float4 v3 = *(const float4*)(vr + 12);
            o[0]  = fmaf(a, v0.x, o[0]);  o[1]  = fmaf(a, v0.y, o[1]);
            o[2]  = fmaf(a, v0.z, o[2]);  o[3]  = fmaf(a, v0.w, o[3]);
            o[4]  = fmaf(a, v1.x, o[4]);  o[5]  = fmaf(a, v1.y, o[5]);
            o[6]  = fmaf(a, v1.z, o[6]);  o[7]  = fmaf(a, v1.w, o[7]);
            o[8]  = fmaf(a, v2.x, o[8]);  o[9]  = fmaf(a, v2.y, o[9]);
            o[10] = fmaf(a, v2.z, o[10]); o[11] = fmaf(a, v2.w, o[11]);
            o[12] = fmaf(a, v3.x, o[12]); o[13] = fmaf(a, v3.y, o[13]);
            o[14] = fmaf(a, v3.z, o[14]); o[15] = fmaf(a, v3.w, o[15]);
        }
    }

#pragma unroll
    for (int j = 0; j < 16; j++) o[j] = rnd_tf32(o[j]);

    float* op = ATT + (size_t)(n * 64 + s) * 512 + (size_t)h * 64 + e0;
    *(float4*)(op + 0)  = make_float4(o[0],  o[1],  o[2],  o[3]);
    *(float4*)(op + 4)  = make_float4(o[4],  o[5],  o[6],  o[7]);
    *(float4*)(op + 8)  = make_float4(o[8],  o[9],  o[10], o[11]);
    *(float4*)(op + 12) = make_float4(o[12], o[13], o[14], o[15]);
}

// ---------------------------------------------------------------------------
// LayerNorm (optionally tf32-round output) + pool
// ---------------------------------------------------------------------------
__global__ void k_ln(const float* __restrict__ in, const float* __restrict__ gam,
                     const float* __restrict__ bet, float* __restrict__ outp, int rnd) {
    int r = blockIdx.x;
    if (r >= g_maxn * 64) return;
    int t = threadIdx.x;
    float4 v = ((const float4*)(in + (size_t)r * 512))[t];
    float s  = v.x + v.y + v.z + v.w;
    float ss = fmaf(v.x, v.x, fmaf(v.y, v.y, fmaf(v.z, v.z, v.w * v.w)));
#pragma unroll
    for (int o = 16; o; o >>= 1) {
        s  += __shfl_xor_sync(0xffffffffu, s,  o);
        ss += __shfl_xor_sync(0xffffffffu, ss, o);
    }
    __shared__ float sh[8];
    if ((t & 31) == 0) { sh[t >> 5] = s; sh[4 + (t >> 5)] = ss; }
    __syncthreads();
    s  = sh[0] + sh[1] + sh[2] + sh[3];
    ss = sh[4] + sh[5] + sh[6] + sh[7];
    float mean = s * (1.f / 512.f);
    float var  = ss * (1.f / 512.f) - mean * mean;
    float inv  = rsqrtf(var + 1e-5f);
    float4 g4 = ((const float4*)gam)[t];
    float4 b4 = ((const float4*)bet)[t];
    float4 o4;
    o4.x = (v.x - mean) * inv * g4.x + b4.x;
    o4.y = (v.y - mean) * inv * g4.y + b4.y;
    o4.z = (v.z - mean) * inv * g4.z + b4.z;
    o4.w = (v.w - mean) * inv * g4.w + b4.w;
    if (rnd) {
        o4.x = rnd_tf32(o4.x); o4.y = rnd_tf32(o4.y);
        o4.z = rnd_tf32(o4.z); o4.w = rnd_tf32(o4.w);
    }
    ((float4*)(outp + (size_t)r * 512))[t] = o4;
}

__global__ void k_pool(const float* __restrict__ Xf, float* __restrict__ out) {
    int g = blockIdx.x;
    int d = threadIdx.x;
    int mx = g_maxn;
    const float* p = Xf + (size_t)g * 512 + d;
    const size_t stride = 64 * 512;
    float s0 = 0.f, s1 = 0.f, s2 = 0.f, s3 = 0.f;
    int n = 0;
    for (; n + 4 <= mx; n += 4) {
        s0 += p[(size_t)(n + 0) * stride];
        s1 += p[(size_t)(n + 1) * stride];
        s2 += p[(size_t)(n + 2) * stride];
        s3 += p[(size_t)(n + 3) * stride];
    }
    for (; n < mx; n++) s0 += p[(size_t)n * stride];
    out[g * 512 + d] = (s0 + s1 + s2 + s3) / (float)mx;
}

// ---------------------------------------------------------------------------
// Launch
// ---------------------------------------------------------------------------
extern "C" void kernel_launch(void* const* d_in, const int* in_sizes, int n_in,
                              void* d_out, int out_size) {
    const float* emb  = (const float*)d_in[0];
    const int*   sidx = (const int*)  d_in[1];
    const float* W_in = (const float*)d_in[2];
    const float* b_in = (const float*)d_in[3];
    const float* W_o  = (const float*)d_in[4];
    const float* b_o  = (const float*)d_in[5];
    const float* ln1g = (const float*)d_in[6];
    const float* ln1b = (const float*)d_in[7];
    const float* W1   = (const float*)d_in[8];
    const float* b1   = (const float*)d_in[9];
    const float* W2   = (const float*)d_in[10];
    const float* b2   = (const float*)d_in[11];
    const float* ln2g = (const float*)d_in[12];
    const float* ln2b = (const float*)d_in[13];
    float* out = (float*)d_out;
    (void)n_in; (void)out_size;

    int N = in_sizes[0] / 512;

    float *pX, *pQKV, *pATT, *pTMP, *pHID, *pWr;
    cudaGetSymbolAddress((void**)&pX,   g_X);
    cudaGetSymbolAddress((void**)&pQKV, g_QKV);
    cudaGetSymbolAddress((void**)&pATT, g_ATT);
    cudaGetSymbolAddress((void**)&pTMP, g_TMP);
    cudaGetSymbolAddress((void**)&pHID, g_HID);
    cudaGetSymbolAddress((void**)&pWr,  g_Wr);

    float* rWin = pWr;                 // 786432
    float* rWo  = pWr + 786432;        // 262144
    float* rW1  = pWr + 1048576;       // 524288
    float* rW2  = pWr + 1572864;       // 524288

    cudaFuncSetAttribute(k_tgemm, cudaFuncAttributeMaxDynamicSharedMemorySize,
                         (int)TG_SMEM_BYTES);

    const int GY = ROWS_CAP / 128;     // 1280 row tiles (beyond-M blocks exit)

    k_meta<<<1, 128>>>(sidx, N);
    k_zeropad<<<64, 256>>>();
    k_scatter<<<N, 128>>>(emb, sidx);
    k_roundw<<<768, 256>>>(W_in, rWin, 196608);
    k_roundw<<<256, 256>>>(W_o,  rWo,   65536);
    k_roundw<<<512, 256>>>(W1,   rW1,  131072);
    k_roundw<<<512, 256>>>(W2,   rW2,  131072);

    // QKV = X @ W_in^T + b_in                      [M, 1536]
    k_tgemm<<<dim3(6, GY), 256, TG_SMEM_BYTES>>>(pX, rWin, b_in, nullptr, pQKV, 1536, 512, 0, 0);

    // attention                                     -> ATT [M, 512] (rounded)
    k_attn<<<dim3(CAP, 8), 256>>>(pQKV, pATT);

    // TMP = ATT @ W_o^T + b_o + X                  [M, 512]
    k_tgemm<<<dim3(2, GY), 256, TG_SMEM_BYTES>>>(pATT, rWo, b_o, pX, pTMP, 512, 512, 0, 0);

    // Y1 = LN1(TMP) -> X (rounded: GEMM A-operand + residual)
    k_ln<<<ROWS_CAP, 128>>>(pTMP, ln1g, ln1b, pX, 1);

    // HID = relu(Y1 @ W1^T + b1)                   [M, 1024] (rounded)
    k_tgemm<<<dim3(4, GY), 256, TG_SMEM_BYTES>>>(pX, rW1, b1, nullptr, pHID, 1024, 512, 1, 1);

    // TMP = HID @ W2^T + b2 + Y1                   [M, 512]
    k_tgemm<<<dim3(2, GY), 256, TG_SMEM_BYTES>>>(pHID, rW2, b2, pX, pTMP, 512, 1024, 0, 0);

    // X2 = LN2(TMP) -> ATT (no rounding; feeds pool only)
    k_ln<<<ROWS_CAP, 128>>>(pTMP, ln2g, ln2b, pATT, 0);

    k_pool<<<64, 512>>>(pATT, out);
}

// round 9
// speedup vs baseline: 1.5427x; 1.5427x over previous
#include <cuda_runtime.h>
#include <math.h>
#include <stdint.h>

// ---------------------------------------------------------------------------
// Problem: D=512, H=8 (e=64), B=64 studies, N=131072 cells.
// Padded layout: row r = n*64 + g. max_n data-dependent; CAP upper bound.
// All GEMM operands tf32-rounded AT THE PRODUCER -> raw fp32 bits into
// mma.sync (HW truncation is identity on pre-rounded values).
// ---------------------------------------------------------------------------
#define CAP       2560
#define ROWS_CAP  (CAP * 64)   // 163840

__device__ int g_maxn;
__device__ int g_starts[65];
__device__ int g_counts[64];

__device__ float g_X  [(size_t)ROWS_CAP * 512];
__device__ float g_QKV[(size_t)ROWS_CAP * 1536];
__device__ float g_ATT[(size_t)ROWS_CAP * 512];
__device__ float g_TMP[(size_t)ROWS_CAP * 512];
__device__ float g_HID[(size_t)ROWS_CAP * 1024];
__device__ float g_Wr [2097152];   // rounded W_in | W_o | W1 | W2

__device__ __forceinline__ uint32_t f2tf32(float f) {
    uint32_t r;
    asm("cvt.rna.tf32.f32 %0, %1;" : "=r"(r) : "f"(f));
    return r;
}
__device__ __forceinline__ float rnd_tf32(float f) {
    return __uint_as_float(f2tf32(f));
}

// ---------------------------------------------------------------------------
// Meta / zeropad / scatter / weight rounding
// ---------------------------------------------------------------------------
__global__ void k_meta(const int* __restrict__ idx, int N) {
    __shared__ int st[65];
    __shared__ int smax;
    int t = threadIdx.x;
    if (t == 0) smax = 0;
    if (t <= 64) {
        if (t == 64) st[64] = N;
        else {
            int lo = 0, hi = N;
            while (lo < hi) { int mid = (lo + hi) >> 1; if (idx[mid] < t) lo = mid + 1; else hi = mid; }
            st[t] = lo;
        }
    }
    __syncthreads();
    if (t < 64) {
        int c = st[t + 1] - st[t];
        g_starts[t] = st[t];
        g_counts[t] = c;
        atomicMax(&smax, c);
    }
    if (t == 64) g_starts[64] = N;
    __syncthreads();
    if (t == 0) g_maxn = (smax < CAP) ? smax : CAP;
}

__global__ void k_zeropad() {
    int g = blockIdx.x;
    int c0 = g_counts[g];
    int rows = g_maxn - c0;
    if (rows <= 0) return;
    float4 z = make_float4(0.f, 0.f, 0.f, 0.f);
    for (int w = threadIdx.x; w < rows * 128; w += 256) {
        int n = c0 + (w >> 7);
        int j = w & 127;
        ((float4*)(g_X + (size_t)((n << 6) + g) * 512))[j] = z;
    }
}

__global__ void k_scatter(const float* __restrict__ emb, const int* __restrict__ idx) {
    int i = blockIdx.x;
    int g = idx[i];
    int n = i - g_starts[g];
    float4 v = ((const float4*)(emb + (size_t)i * 512))[threadIdx.x];
    v.x = rnd_tf32(v.x); v.y = rnd_tf32(v.y); v.z = rnd_tf32(v.z); v.w = rnd_tf32(v.w);
    ((float4*)(g_X + (size_t)(n * 64 + g) * 512))[threadIdx.x] = v;
}

__global__ void k_roundw(const float* __restrict__ s, float* __restrict__ d, int n4) {
    int i = blockIdx.x * 256 + threadIdx.x;
    if (i >= n4) return;
    float4 v = ((const float4*)s)[i];
    v.x = rnd_tf32(v.x); v.y = rnd_tf32(v.y); v.z = rnd_tf32(v.z); v.w = rnd_tf32(v.w);
    ((float4*)d)[i] = v;
}

// ---------------------------------------------------------------------------
// tf32 tensor-core GEMM: BM=128, BN=128, BK=32.
// 4 warps (2x2), warp tile 64x64 (4 mt x 8 n8 m16n8k8). 128 threads.
// 3-stage cp.async ring; single-buffered ldmatrix fragments; ~180 regs ->
// 2 CTAs/SM (barrier/epilogue overlap) with low smem-read redundancy.
// ---------------------------------------------------------------------------
#define SROW 36
#define A_W   (128 * SROW)
#define B_W   (128 * SROW)
#define STAGE_B ((A_W + B_W) * 4u)      // 36864 bytes
#define TG_SMEM_BYTES (3u * STAGE_B)    // 110592

__device__ __forceinline__ void mma_tf32(float c[4],
                                         uint32_t a0, uint32_t a1, uint32_t a2, uint32_t a3,
                                         uint32_t b0, uint32_t b1) {
    asm volatile(
        "mma.sync.aligned.m16n8k8.row.col.f32.tf32.tf32.f32 "
        "{%0,%1,%2,%3}, {%4,%5,%6,%7}, {%8,%9}, {%0,%1,%2,%3};"
        : "+f"(c[0]), "+f"(c[1]), "+f"(c[2]), "+f"(c[3])
        : "r"(a0), "r"(a1), "r"(a2), "r"(a3), "r"(b0), "r"(b1));
}
#define LDSM4(f, a) \
    asm volatile("ldmatrix.sync.aligned.m8n8.x4.shared.b16 {%0,%1,%2,%3}, [%4];" \
                 : "=r"((f)[0]), "=r"((f)[1]), "=r"((f)[2]), "=r"((f)[3]) : "r"(a))

__global__ __launch_bounds__(128, 2)
void k_tgemm(const float* __restrict__ A, const float* __restrict__ Bw,
             const float* __restrict__ bias, const float* __restrict__ resid,
             float* __restrict__ C, int Ncols, int K, int relu, int round_out)
{
    int M = g_maxn * 64;
    int row0 = blockIdx.y * 128;
    if (row0 >= M) return;
    int col0 = blockIdx.x * 128;

    int tid  = threadIdx.x;
    int lane = tid & 31;
    int wid  = tid >> 5;       // 0..3
    int wm   = wid & 1;        // 2 warp rows x 64
    int wn   = wid >> 1;       // 2 warp cols x 64
    int g    = lane >> 2;
    int tg   = lane & 3;

    extern __shared__ uint32_t sm[];
    uint32_t smb = (uint32_t)__cvta_generic_to_shared(sm);

    const float* Abase = A  + (size_t)row0 * K;
    const float* Bbase = Bw + (size_t)col0 * K;

    int srow = tid >> 3;       // 0..15
    int sc4  = tid & 7;

    // LDSM lane byte offsets
    uint32_t rowA = (uint32_t)(((wm * 64 + (lane & 15)) * SROW + (lane >> 4) * 4) * 4);
    uint32_t rowB = (uint32_t)(((wn * 64 + (lane & 7) + (lane >> 4) * 8) * SROW
                                + ((lane >> 3) & 1) * 4) * 4);

    float c[4][8][4];
#pragma unroll
    for (int i = 0; i < 4; i++)
#pragma unroll
        for (int j = 0; j < 8; j++)
#pragma unroll
            for (int k = 0; k < 4; k++) c[i][j][k] = 0.f;

    const int KT = K >> 5;

#define STAGE(kt_)  do {                                                          \
        int _kt = (kt_);                                                          \
        uint32_t _sb = smb + (uint32_t)(_kt % 3) * STAGE_B;                       \
        int _ko = _kt * 32 + sc4 * 4;                                             \
        _Pragma("unroll")                                                         \
        for (int _i = 0; _i < 8; _i++) {                                          \
            int _row = srow + 16 * _i;                                            \
            uint32_t _d = _sb + (uint32_t)((_row * SROW + sc4 * 4) * 4);          \
            int _ok = (row0 + _row) < M;                                          \
            const float* _sa = Abase + (size_t)(_ok ? _row : 0) * K + _ko;        \
            int _sz = _ok ? 16 : 0;                                               \
            asm volatile("cp.async.cg.shared.global [%0], [%1], 16, %2;"          \
                         :: "r"(_d), "l"(_sa), "r"(_sz));                         \
        }                                                                         \
        _Pragma("unroll")                                                         \
        for (int _i = 0; _i < 8; _i++) {                                          \
            int _row = srow + 16 * _i;                                            \
            uint32_t _d = _sb + (uint32_t)(A_W * 4)                               \
                        + (uint32_t)((_row * SROW + sc4 * 4) * 4);                \
            const float* _sb2 = Bbase + (size_t)_row * K + _ko;                   \
            asm volatile("cp.async.cg.shared.global [%0], [%1], 16;"              \
                         :: "r"(_d), "l"(_sb2));                                  \
        }                                                                         \
        asm volatile("cp.async.commit_group;");                                   \
    } while (0)

    STAGE(0);
    STAGE(1);

    uint32_t fa[4][4], fb[4][4];

    for (int kt = 0; kt < KT; kt++) {
        if (kt + 1 < KT) { asm volatile("cp.async.wait_group 1;"); }
        else             { asm volatile("cp.async.wait_group 0;"); }
        __syncthreads();
        if (kt + 2 < KT) STAGE(kt + 2);   // overwrites buffer consumed at kt-1

        uint32_t aB = smb + (uint32_t)(kt % 3) * STAGE_B + rowA;
        uint32_t bB = smb + (uint32_t)(kt % 3) * STAGE_B + (uint32_t)(A_W * 4) + rowB;

#pragma unroll
        for (int kk = 0; kk < 4; kk++) {
#pragma unroll
            for (int mt = 0; mt < 4; mt++)
                LDSM4(fa[mt], aB + (uint32_t)((mt * 16 * SROW + kk * 8) * 4));
#pragma unroll
            for (int p = 0; p < 4; p++)
                LDSM4(fb[p], bB + (uint32_t)((p * 16 * SROW + kk * 8) * 4));
#pragma unroll
            for (int p = 0; p < 4; p++)
#pragma unroll
                for (int mt = 0; mt < 4; mt++) {
                    mma_tf32(c[mt][2 * p],
                             fa[mt][0], fa[mt][1], fa[mt][2], fa[mt][3],
                             fb[p][0], fb[p][1]);
                    mma_tf32(c[mt][2 * p + 1],
                             fa[mt][0], fa[mt][1], fa[mt][2], fa[mt][3],
                             fb[p][2], fb[p][3]);
                }
        }
    }

    // epilogue: bias (+resid) (relu) (tf32 round if output feeds a GEMM)
#pragma unroll
    for (int mt = 0; mt < 4; mt++) {
        int r0 = row0 + wm * 64 + mt * 16 + g;
        int r1 = r0 + 8;
#pragma unroll
        for (int nt = 0; nt < 8; nt++) {
            int cc = col0 + wn * 64 + nt * 8 + 2 * tg;
            float2 bv = *(const float2*)(bias + cc);
            if (r0 < M) {
                float2 o = make_float2(c[mt][nt][0] + bv.x, c[mt][nt][1] + bv.y);
                if (resid) {
                    float2 rv = *(const float2*)(resid + (size_t)r0 * Ncols + cc);
                    o.x += rv.x; o.y += rv.y;
                }
                if (relu) { o.x = fmaxf(o.x, 0.f); o.y = fmaxf(o.y, 0.f); }
                if (round_out) { o.x = rnd_tf32(o.x); o.y = rnd_tf32(o.y); }
                *(float2*)(C + (size_t)r0 * Ncols + cc) = o;
            }
            if (r1 < M) {
                float2 o = make_float2(c[mt][nt][2] + bv.x, c[mt][nt][3] + bv.y);
                if (resid) {
                    float2 rv = *(const float2*)(resid + (size_t)r1 * Ncols + cc);
                    o.x += rv.x; o.y += rv.y;
                }
                if (relu) { o.x = fmaxf(o.x, 0.f); o.y = fmaxf(o.y, 0.f); }
                if (round_out) { o.x = rnd_tf32(o.x); o.y = rnd_tf32(o.y); }
                *(float2*)(C + (size_t)r1 * Ncols + cc) = o;
            }
        }
    }
#undef STAGE
}

// ---------------------------------------------------------------------------
// Attention: one block per (position n, head h). Output tf32-rounded.
// ---------------------------------------------------------------------------
__global__ __launch_bounds__(256)
void k_attn(const float* __restrict__ QKV, float* __restrict__ ATT) {
    int n = blockIdx.x;
    if (n >= g_maxn) return;
    int h = blockIdx.y;

    __shared__ float Qt[64][64];
    __shared__ float Kt[64][64];
    __shared__ float V [64][64];

    int tid = threadIdx.x;
    size_t base = (size_t)n * 64 * 1536 + (size_t)h * 64;
    for (int idx = tid; idx < 4096; idx += 256) {
        int s = idx >> 6, e = idx & 63;
        size_t rb = base + (size_t)s * 1536 + e;
        Qt[e][s] = QKV[rb];
        Kt[e][s] = QKV[rb + 512];
        V [s][e] = QKV[rb + 1024];
    }
    __syncthreads();

    int s  = tid >> 2;
    int qd = tid & 3;
    int t0 = qd << 4;

    float acc[16];
#pragma unroll
    for (int j = 0; j < 16; j++) acc[j] = 0.f;

#pragma unroll 4
    for (int e = 0; e < 64; e++) {
        float  qv = Qt[e][s];
        float4 k0 = *(const float4*)&Kt[e][t0 + 0];
        float4 k1 = *(const float4*)&Kt[e][t0 + 4];
        float4 k2 = *(const float4*)&Kt[e][t0 + 8];
        float4 k3 = *(const float4*)&Kt[e][t0 + 12];
        acc[0]  = fmaf(qv, k0.x, acc[0]);  acc[1]  = fmaf(qv, k0.y, acc[1]);
        acc[2]  = fmaf(qv, k0.z, acc[2]);  acc[3]  = fmaf(qv, k0.w, acc[3]);
        acc[4]  = fmaf(qv, k1.x, acc[4]);  acc[5]  = fmaf(qv, k1.y, acc[5]);
        acc[6]  = fmaf(qv, k1.z, acc[6]);  acc[7]  = fmaf(qv, k1.w, acc[7]);
        acc[8]  = fmaf(qv, k2.x, acc[8]);  acc[9]  = fmaf(qv, k2.y, acc[9]);
        acc[10] = fmaf(qv, k2.z, acc[10]); acc[11] = fmaf(qv, k2.w, acc[11]);
        acc[12] = fmaf(qv, k3.x, acc[12]); acc[13] = fmaf(qv, k3.y, acc[13]);
        acc[14] = fmaf(qv, k3.z, acc[14]); acc[15] = fmaf(qv, k3.w, acc[15]);
    }

    float mx = -1e30f;
#pragma unroll
    for (int j = 0; j < 16; j++) {
        float v = acc[j] * 0.125f;
        if (g_counts[t0 + j] <= n) v = -1e30f;
        acc[j] = v;
        mx = fmaxf(mx, v);
    }
    mx = fmaxf(mx, __shfl_xor_sync(0xffffffffu, mx, 1, 4));
    mx = fmaxf(mx, __shfl_xor_sync(0xffffffffu, mx, 2, 4));
    float sum = 0.f;
#pragma unroll
    for (int j = 0; j < 16; j++) { float p = __expf(acc[j] - mx); acc[j] = p; sum += p; }
    sum += __shfl_xor_sync(0xffffffffu, sum, 1, 4);
    sum += __shfl_xor_sync(0xffffffffu, sum, 2, 4);
    float inv = 1.f / sum;
#pragma unroll
    for (int j = 0; j < 16; j++) acc[j] *= inv;

    float o[16];
#pragma unroll
    for (int j = 0; j < 16; j++) o[j] = 0.f;
    int e0 = qd << 4;
#pragma unroll
    for (int tq = 0; tq < 4; tq++) {
#pragma unroll
        for (int j2 = 0; j2 < 16; j2++) {
            float a = __shfl_sync(0xffffffffu, acc[j2], tq, 4);
            const float* vr = &V[tq * 16 + j2][e0];
            float4 v0 = *(const float4*)(vr + 0);
            float4 v1 = *(const float4*)(vr + 4);
            float4 v2 = *(const float4*)(vr + 8);
            float4 v3 = *(const float4*)(vr + 12);
            o[0]  = fmaf(a, v0.x, o[0]);  o[1]  = fmaf(a, v0.y, o[1]);
            o[2]  = fmaf(a, v0.z, o[2]);  o[3]  = fmaf(a, v0.w, o[3]);
            o[4]  = fmaf(a, v1.x, o[4]);  o[5]  = fmaf(a, v1.y, o[5]);
            o[6]  = fmaf(a, v1.z, o[6]);  o[7]  = fmaf(a, v1.w, o[7]);
            o[8]  = fmaf(a, v2.x, o[8]);  o[9]  = fmaf(a, v2.y, o[9]);
            o[10] = fmaf(a, v2.z, o[10]); o[11] = fmaf(a, v2.w, o[11]);
            o[12] = fmaf(a, v3.x, o[12]); o[13] = fmaf(a, v3.y, o[13]);
            o[14] = fmaf(a, v3.z, o[14]); o[15] = fmaf(a, v3.w, o[15]);
        }
    }

#pragma unroll
    for (int j = 0; j < 16; j++) o[j] = rnd_tf32(o[j]);

    float* op = ATT + (size_t)(n * 64 + s) * 512 + (size_t)h * 64 + e0;
    *(float4*)(op + 0)  = make_float4(o[0],  o[1],  o[2],  o[3]);
    *(float4*)(op + 4)  = make_float4(o[4],  o[5],  o[6],  o[7]);
    *(float4*)(op + 8)  = make_float4(o[8],  o[9],  o[10], o[11]);
    *(float4*)(op + 12) = make_float4(o[12], o[13], o[14], o[15]);
}

// ---------------------------------------------------------------------------
// LayerNorm (optionally tf32-round output) + pool
// ---------------------------------------------------------------------------
__global__ void k_ln(const float* __restrict__ in, const float* __restrict__ gam,
                     const float* __restrict__ bet, float* __restrict__ outp, int rnd) {
    int r = blockIdx.x;
    if (r >= g_maxn * 64) return;
    int t = threadIdx.x;
    float4 v = ((const float4*)(in + (size_t)r * 512))[t];
    float s  = v.x + v.y + v.z + v.w;
    float ss = fmaf(v.x, v.x, fmaf(v.y, v.y, fmaf(v.z, v.z, v.w * v.w)));
#pragma unroll
    for (int o = 16; o; o >>= 1) {
        s  += __shfl_xor_sync(0xffffffffu, s,  o);
        ss += __shfl_xor_sync(0xffffffffu, ss, o);
    }
    __shared__ float sh[8];
    if ((t & 31) == 0) { sh[t >> 5] = s; sh[4 + (t >> 5)] = ss; }
    __syncthreads();
    s  = sh[0] + sh[1] + sh[2] + sh[3];
    ss = sh[4] + sh[5] + sh[6] + sh[7];
    float mean = s * (1.f / 512.f);
    float var  = ss * (1.f / 512.f) - mean * mean;
    float inv  = rsqrtf(var + 1e-5f);
    float4 g4 = ((const float4*)gam)[t];
    float4 b4 = ((const float4*)bet)[t];
    float4 o4;
    o4.x = (v.x - mean) * inv * g4.x + b4.x;
    o4.y = (v.y - mean) * inv * g4.y + b4.y;
    o4.z = (v.z - mean) * inv * g4.z + b4.z;
    o4.w = (v.w - mean) * inv * g4.w + b4.w;
    if (rnd) {
        o4.x = rnd_tf32(o4.x); o4.y = rnd_tf32(o4.y);
        o4.z = rnd_tf32(o4.z); o4.w = rnd_tf32(o4.w);
    }
    ((float4*)(outp + (size_t)r * 512))[t] = o4;
}

__global__ void k_pool(const float* __restrict__ Xf, float* __restrict__ out) {
    int g = blockIdx.x;
    int d = threadIdx.x;
    int mx = g_maxn;
    const float* p = Xf + (size_t)g * 512 + d;
    const size_t stride = 64 * 512;
    float s0 = 0.f, s1 = 0.f, s2 = 0.f, s3 = 0.f;
    int n = 0;
    for (; n + 4 <= mx; n += 4) {
        s0 += p[(size_t)(n + 0) * stride];
        s1 += p[(size_t)(n + 1) * stride];
        s2 += p[(size_t)(n + 2) * stride];
        s3 += p[(size_t)(n + 3) * stride];
    }
    for (; n < mx; n++) s0 += p[(size_t)n * stride];
    out[g * 512 + d] = (s0 + s1 + s2 + s3) / (float)mx;
}

// ---------------------------------------------------------------------------
// Launch
// ---------------------------------------------------------------------------
extern "C" void kernel_launch(void* const* d_in, const int* in_sizes, int n_in,
                              void* d_out, int out_size) {
    const float* emb  = (const float*)d_in[0];
    const int*   sidx = (const int*)  d_in[1];
    const float* W_in = (const float*)d_in[2];
    const float* b_in = (const float*)d_in[3];
    const float* W_o  = (const float*)d_in[4];
    const float* b_o  = (const float*)d_in[5];
    const float* ln1g = (const float*)d_in[6];
    const float* ln1b = (const float*)d_in[7];
    const float* W1   = (const float*)d_in[8];
    const float* b1   = (const float*)d_in[9];
    const float* W2   = (const float*)d_in[10];
    const float* b2   = (const float*)d_in[11];
    const float* ln2g = (const float*)d_in[12];
    const float* ln2b = (const float*)d_in[13];
    float* out = (float*)d_out;
    (void)n_in; (void)out_size;

    int N = in_sizes[0] / 512;

    float *pX, *pQKV, *pATT, *pTMP, *pHID, *pWr;
    cudaGetSymbolAddress((void**)&pX,   g_X);
    cudaGetSymbolAddress((void**)&pQKV, g_QKV);
    cudaGetSymbolAddress((void**)&pATT, g_ATT);
    cudaGetSymbolAddress((void**)&pTMP, g_TMP);
    cudaGetSymbolAddress((void**)&pHID, g_HID);
    cudaGetSymbolAddress((void**)&pWr,  g_Wr);

    float* rWin = pWr;                 // 786432
    float* rWo  = pWr + 786432;        // 262144
    float* rW1  = pWr + 1048576;       // 524288
    float* rW2  = pWr + 1572864;       // 524288

    cudaFuncSetAttribute(k_tgemm, cudaFuncAttributeMaxDynamicSharedMemorySize,
                         (int)TG_SMEM_BYTES);

    const int GY = ROWS_CAP / 128;     // 1280 row tiles (beyond-M blocks exit)

    k_meta<<<1, 128>>>(sidx, N);
    k_zeropad<<<64, 256>>>();
    k_scatter<<<N, 128>>>(emb, sidx);
    k_roundw<<<768, 256>>>(W_in, rWin, 196608);
    k_roundw<<<256, 256>>>(W_o,  rWo,   65536);
    k_roundw<<<512, 256>>>(W1,   rW1,  131072);
    k_roundw<<<512, 256>>>(W2,   rW2,  131072);

    // QKV = X @ W_in^T + b_in                      [M, 1536]
    k_tgemm<<<dim3(12, GY), 128, TG_SMEM_BYTES>>>(pX, rWin, b_in, nullptr, pQKV, 1536, 512, 0, 0);

    // attention                                     -> ATT [M, 512] (rounded)
    k_attn<<<dim3(CAP, 8), 256>>>(pQKV, pATT);

    // TMP = ATT @ W_o^T + b_o + X                  [M, 512]
    k_tgemm<<<dim3(4, GY), 128, TG_SMEM_BYTES>>>(pATT, rWo, b_o, pX, pTMP, 512, 512, 0, 0);

    // Y1 = LN1(TMP) -> X (rounded: GEMM A-operand + residual)
    k_ln<<<ROWS_CAP, 128>>>(pTMP, ln1g, ln1b, pX, 1);

    // HID = relu(Y1 @ W1^T + b1)                   [M, 1024] (rounded)
    k_tgemm<<<dim3(8, GY), 128, TG_SMEM_BYTES>>>(pX, rW1, b1, nullptr, pHID, 1024, 512, 1, 1);

    // TMP = HID @ W2^T + b2 + Y1                   [M, 512]
    k_tgemm<<<dim3(4, GY), 128, TG_SMEM_BYTES>>>(pHID, rW2, b2, pX, pTMP, 512, 1024, 0, 0);

    // X2 = LN2(TMP) -> ATT (no rounding; feeds pool only)
    k_ln<<<ROWS_CAP, 128>>>(pTMP, ln2g, ln2b, pATT, 0);

    k_pool<<<64, 512>>>(pATT, out);
}

// round 10
// speedup vs baseline: 2.0913x; 1.3557x over previous
#include <cuda_runtime.h>
#include <cuda_fp16.h>
#include <math.h>
#include <stdint.h>

// ---------------------------------------------------------------------------
// Problem: D=512, H=8 (e=64), B=64 studies, N=131072 cells.
// Padded layout: row r = n*64 + g. max_n data-dependent; CAP upper bound.
// GEMM datapath is fp16 (11-bit mantissa == tf32): all GEMM operands are
// fp16-rounded at the producer; mma.sync.m16n8k16.f16 with fp32 accumulate
// runs at 2x the tf32 rate. GEMM outputs (QKV/TMP) stay fp32.
// ---------------------------------------------------------------------------
#define CAP       2560
#define ROWS_CAP  (CAP * 64)   // 163840

__device__ int g_maxn;
__device__ int g_starts[65];
__device__ int g_counts[64];

__device__ __align__(128) __half g_Xh [(size_t)ROWS_CAP * 512];   // X (fp16)
__device__ float  g_QKV[(size_t)ROWS_CAP * 1536];                  // fp32
__device__ __align__(128) __half g_ATTh[(size_t)ROWS_CAP * 512];  // attn out
__device__ float  g_TMP[(size_t)ROWS_CAP * 512];                   // fp32
__device__ __align__(128) __half g_Y1h[(size_t)ROWS_CAP * 512];   // LN1 out
__device__ __align__(128) __half g_HIDh[(size_t)ROWS_CAP * 1024]; // FF hidden
__device__ __align__(128) __half g_Wh [2097152];  // fp16 W_in | W_o | W1 | W2

// ---------------------------------------------------------------------------
// Meta / zeropad / scatter / weight conversion
// ---------------------------------------------------------------------------
__global__ void k_meta(const int* __restrict__ idx, int N) {
    __shared__ int st[65];
    __shared__ int smax;
    int t = threadIdx.x;
    if (t == 0) smax = 0;
    if (t <= 64) {
        if (t == 64) st[64] = N;
        else {
            int lo = 0, hi = N;
            while (lo < hi) { int mid = (lo + hi) >> 1; if (idx[mid] < t) lo = mid + 1; else hi = mid; }
            st[t] = lo;
        }
    }
    __syncthreads();
    if (t < 64) {
        int c = st[t + 1] - st[t];
        g_starts[t] = st[t];
        g_counts[t] = c;
        atomicMax(&smax, c);
    }
    if (t == 64) g_starts[64] = N;
    __syncthreads();
    if (t == 0) g_maxn = (smax < CAP) ? smax : CAP;
}

// zero fp16 padding rows of X
__global__ void k_zeropad() {
    int g = blockIdx.x;
    int c0 = g_counts[g];
    int rows = g_maxn - c0;
    if (rows <= 0) return;
    uint4 z = make_uint4(0u, 0u, 0u, 0u);
    for (int w = threadIdx.x; w < rows * 64; w += 256) {
        int n = c0 + (w >> 6);
        int j = w & 63;                 // 64 x 16B per 512-half row
        ((uint4*)(g_Xh + (size_t)((n << 6) + g) * 512))[j] = z;
    }
}

// scatter + fp16 round (X is a GEMM A-operand and a residual)
__global__ void k_scatter(const float* __restrict__ emb, const int* __restrict__ idx) {
    int i = blockIdx.x;
    int g = idx[i];
    int n = i - g_starts[g];
    int t = threadIdx.x;                // 128: 4 floats each
    float4 v = ((const float4*)(emb + (size_t)i * 512))[t];
    __half2 h0 = __floats2half2_rn(v.x, v.y);
    __half2 h1 = __floats2half2_rn(v.z, v.w);
    __half2* d = (__half2*)(g_Xh + (size_t)(n * 64 + g) * 512 + t * 4);
    d[0] = h0; d[1] = h1;
}

// convert a weight matrix (fp32) into fp16
__global__ void k_cvtw(const float* __restrict__ s, __half* __restrict__ d, int n4) {
    int i = blockIdx.x * 256 + threadIdx.x;
    if (i >= n4) return;
    float4 v = ((const float4*)s)[i];
    __half2* p = (__half2*)(d + (size_t)i * 4);
    p[0] = __floats2half2_rn(v.x, v.y);
    p[1] = __floats2half2_rn(v.z, v.w);
}

// ---------------------------------------------------------------------------
// fp16 tensor-core GEMM: C[M,Nc] = A[M,K]*Bw[Nc,K]^T + bias (+resid)(relu)
// BM=BN=128, BK=32 halves. 8 warps, warp tile 64x32 (4x4 m16n8k16, kk=2).
// 3-stage cp.async ring (halves straight from gmem), native b16 ldmatrix,
// register double-buffer across kk. SROW_H=40 halves -> conflict-free LDSM.
// ---------------------------------------------------------------------------
#define SROW_H 40
#define A_BYTES (128u * SROW_H * 2u)    // 10240
#define STAGE_B (2u * A_BYTES)          // 20480
#define TG_SMEM_BYTES (3u * STAGE_B)    // 61440

__device__ __forceinline__ void mma_f16(float c[4],
                                        uint32_t a0, uint32_t a1, uint32_t a2, uint32_t a3,
                                        uint32_t b0, uint32_t b1) {
    asm volatile(
        "mma.sync.aligned.m16n8k16.row.col.f32.f16.f16.f32 "
        "{%0,%1,%2,%3}, {%4,%5,%6,%7}, {%8,%9}, {%0,%1,%2,%3};"
        : "+f"(c[0]), "+f"(c[1]), "+f"(c[2]), "+f"(c[3])
        : "r"(a0), "r"(a1), "r"(a2), "r"(a3), "r"(b0), "r"(b1));
}
#define LDSM4(f, a) \
    asm volatile("ldmatrix.sync.aligned.m8n8.x4.shared.b16 {%0,%1,%2,%3}, [%4];" \
                 : "=r"((f)[0]), "=r"((f)[1]), "=r"((f)[2]), "=r"((f)[3]) : "r"(a))

__global__ __launch_bounds__(256, 2)
void k_tgemm(const __half* __restrict__ A, const __half* __restrict__ Bw,
             const float* __restrict__ bias, const __half* __restrict__ resid,
             void* __restrict__ Cv, int Ncols, int K, int relu, int out_half)
{
    int M = g_maxn * 64;
    int row0 = blockIdx.y * 128;
    if (row0 >= M) return;
    int col0 = blockIdx.x * 128;

    int tid  = threadIdx.x;
    int lane = tid & 31;
    int wid  = tid >> 5;
    int wm   = wid & 1;        // 2 warp rows x 64
    int wn   = wid >> 1;       // 4 warp cols x 32
    int g    = lane >> 2;
    int tg   = lane & 3;

    extern __shared__ uint32_t sm[];
    uint32_t smb = (uint32_t)__cvta_generic_to_shared(sm);

    const __half* Abase = A  + (size_t)row0 * K;
    const __half* Bbase = Bw + (size_t)col0 * K;

    int srow = tid >> 2;       // 0..63
    int sc   = tid & 3;        // 16B chunk within 64B row

    // LDSM lane byte offsets
    // A (x4): lanes 0-15 -> rows 0-15 @k0; lanes 16-31 -> rows 0-15 @k+8
    uint32_t rowA = (uint32_t)(((wm * 64 + (lane & 15)) * SROW_H + (lane >> 4) * 8) * 2);
    // B (x4 over an nt pair p: 16 n-rows): lanes 0-7 n0-7@k0, 8-15 n8-15@k0,
    //                                      16-23 n0-7@k8, 24-31 n8-15@k8
    uint32_t rowB = (uint32_t)(((wn * 32 + (lane & 7) + ((lane >> 3) & 1) * 8) * SROW_H
                                + (lane >> 4) * 8) * 2);

    float c[4][4][4];
#pragma unroll
    for (int i = 0; i < 4; i++)
#pragma unroll
        for (int j = 0; j < 4; j++)
#pragma unroll
            for (int k = 0; k < 4; k++) c[i][j][k] = 0.f;

    const int KT = K >> 5;     // BK = 32 halves

#define STAGE(kt_)  do {                                                          \
        int _kt = (kt_);                                                          \
        uint32_t _sb = smb + (uint32_t)(_kt % 3) * STAGE_B;                       \
        int _ko = _kt * 32 + sc * 8;                                              \
        _Pragma("unroll")                                                         \
        for (int _i = 0; _i < 2; _i++) {                                          \
            int _row = srow + 64 * _i;                                            \
            uint32_t _d = _sb + (uint32_t)((_row * SROW_H + sc * 8) * 2);         \
            int _ok = (row0 + _row) < M;                                          \
            const __half* _sa = Abase + (size_t)(_ok ? _row : 0) * K + _ko;       \
            int _sz = _ok ? 16 : 0;                                               \
            asm volatile("cp.async.cg.shared.global [%0], [%1], 16, %2;"          \
                         :: "r"(_d), "l"(_sa), "r"(_sz));                         \
            uint32_t _d2 = _d + A_BYTES;                                          \
            const __half* _sb2 = Bbase + (size_t)_row * K + _ko;                  \
            asm volatile("cp.async.cg.shared.global [%0], [%1], 16;"              \
                         :: "r"(_d2), "l"(_sb2));                                 \
        }                                                                         \
        asm volatile("cp.async.commit_group;");                                   \
    } while (0)

    STAGE(0);
    STAGE(1);

    uint32_t fa[2][4][4], fb[2][2][4];

    for (int kt = 0; kt < KT; kt++) {
        if (kt + 1 < KT) { asm volatile("cp.async.wait_group 1;"); }
        else             { asm volatile("cp.async.wait_group 0;"); }
        __syncthreads();
        if (kt + 2 < KT) STAGE(kt + 2);   // overwrites buffer consumed at kt-1

        uint32_t aB = smb + (uint32_t)(kt % 3) * STAGE_B + rowA;
        uint32_t bB = smb + (uint32_t)(kt % 3) * STAGE_B + A_BYTES + rowB;

        // fragments for kk=0 (k16 slice 0)
#pragma unroll
        for (int mt = 0; mt < 4; mt++)
            LDSM4(fa[0][mt], aB + (uint32_t)(mt * 16 * SROW_H * 2));
#pragma unroll
        for (int p = 0; p < 2; p++)
            LDSM4(fb[0][p], bB + (uint32_t)(p * 16 * SROW_H * 2));

#pragma unroll
        for (int kk = 0; kk < 2; kk++) {
            const int cb = kk & 1, nb = cb ^ 1;
            if (kk < 1) {
#pragma unroll
                for (int mt = 0; mt < 4; mt++)
                    LDSM4(fa[nb][mt], aB + (uint32_t)(mt * 16 * SROW_H * 2 + 32));
#pragma unroll
                for (int p = 0; p < 2; p++)
                    LDSM4(fb[nb][p], bB + (uint32_t)(p * 16 * SROW_H * 2 + 32));
            }
#pragma unroll
            for (int p = 0; p < 2; p++)
#pragma unroll
                for (int mt = 0; mt < 4; mt++) {
                    // nt = 2p   uses B regs {m0, m2}; nt = 2p+1 uses {m1, m3}
                    mma_f16(c[mt][2 * p],
                            fa[cb][mt][0], fa[cb][mt][1], fa[cb][mt][2], fa[cb][mt][3],
                            fb[cb][p][0], fb[cb][p][2]);
                    mma_f16(c[mt][2 * p + 1],
                            fa[cb][mt][0], fa[cb][mt][1], fa[cb][mt][2], fa[cb][mt][3],
                            fb[cb][p][1], fb[cb][p][3]);
                }
        }
    }

    // epilogue: bias (+resid fp16) (relu); out fp32 or fp16
    float*  Cf = (float*)Cv;
    __half* Ch = (__half*)Cv;
#pragma unroll
    for (int mt = 0; mt < 4; mt++) {
        int r0 = row0 + wm * 64 + mt * 16 + g;
        int r1 = r0 + 8;
#pragma unroll
        for (int nt = 0; nt < 4; nt++) {
            int cc = col0 + wn * 32 + nt * 8 + 2 * tg;
            float2 bv = *(const float2*)(bias + cc);
#pragma unroll
            for (int half_row = 0; half_row < 2; half_row++) {
                int r = half_row ? r1 : r0;
                if (r >= M) continue;
                float o0 = c[mt][nt][2 * half_row + 0] + bv.x;
                float o1 = c[mt][nt][2 * half_row + 1] + bv.y;
                if (resid) {
                    __half2 rv = *(const __half2*)(resid + (size_t)r * Ncols + cc);
                    float2 rf = __half22float2(rv);
                    o0 += rf.x; o1 += rf.y;
                }
                if (relu) { o0 = fmaxf(o0, 0.f); o1 = fmaxf(o1, 0.f); }
                if (out_half) {
                    *(__half2*)(Ch + (size_t)r * Ncols + cc) = __floats2half2_rn(o0, o1);
                } else {
                    *(float2*)(Cf + (size_t)r * Ncols + cc) = make_float2(o0, o1);
                }
            }
        }
    }
#undef STAGE
}

// ---------------------------------------------------------------------------
// Attention: one block per (position n, head h). QKV fp32 in, ATT fp16 out.
// ---------------------------------------------------------------------------
__global__ __launch_bounds__(256)
void k_attn(const float* __restrict__ QKV, __half* __restrict__ ATT) {
    int n = blockIdx.x;
    if (n >= g_maxn) return;
    int h = blockIdx.y;

    __shared__ float Qt[64][64];
    __shared__ float Kt[64][64];
    __shared__ float V [64][64];

    int tid = threadIdx.x;
    size_t base = (size_t)n * 64 * 1536 + (size_t)h * 64;
    for (int idx = tid; idx < 4096; idx += 256) {
        int s = idx >> 6, e = idx & 63;
        size_t rb = base + (size_t)s * 1536 + e;
        Qt[e][s] = QKV[rb];
        Kt[e][s] = QKV[rb + 512];
        V [s][e] = QKV[rb + 1024];
    }
    __syncthreads();

    int s  = tid >> 2;
    int qd = tid & 3;
    int t0 = qd << 4;

    float acc[16];
#pragma unroll
    for (int j = 0; j < 16; j++) acc[j] = 0.f;

#pragma unroll 4
    for (int e = 0; e < 64; e++) {
        float  qv = Qt[e][s];
        float4 k0 = *(const float4*)&Kt[e][t0 + 0];
        float4 k1 = *(const float4*)&Kt[e][t0 + 4];
        float4 k2 = *(const float4*)&Kt[e][t0 + 8];
        float4 k3 = *(const float4*)&Kt[e][t0 + 12];
        acc[0]  = fmaf(qv, k0.x, acc[0]);  acc[1]  = fmaf(qv, k0.y, acc[1]);
        acc[2]  = fmaf(qv, k0.z, acc[2]);  acc[3]  = fmaf(qv, k0.w, acc[3]);
        acc[4]  = fmaf(qv, k1.x, acc[4]);  acc[5]  = fmaf(qv, k1.y, acc[5]);
        acc[6]  = fmaf(qv, k1.z, acc[6]);  acc[7]  = fmaf(qv, k1.w, acc[7]);
        acc[8]  = fmaf(qv, k2.x, acc[8]);  acc[9]  = fmaf(qv, k2.y, acc[9]);
        acc[10] = fmaf(qv, k2.z, acc[10]); acc[11] = fmaf(qv, k2.w, acc[11]);
        acc[12] = fmaf(qv, k3.x, acc[12]); acc[13] = fmaf(qv, k3.y, acc[13]);
        acc[14] = fmaf(qv, k3.z, acc[14]); acc[15] = fmaf(qv, k3.w, acc[15]);
    }

    float mx = -1e30f;
#pragma unroll
    for (int j = 0; j < 16; j++) {
        float v = acc[j] * 0.125f;
        if (g_counts[t0 + j] <= n) v = -1e30f;
        acc[j] = v;
        mx = fmaxf(mx, v);
    }
    mx = fmaxf(mx, __shfl_xor_sync(0xffffffffu, mx, 1, 4));
    mx = fmaxf(mx, __shfl_xor_sync(0xffffffffu, mx, 2, 4));
    float sum = 0.f;
#pragma unroll
    for (int j = 0; j < 16; j++) { float p = __expf(acc[j] - mx); acc[j] = p; sum += p; }
    sum += __shfl_xor_sync(0xffffffffu, sum, 1, 4);
    sum += __shfl_xor_sync(0xffffffffu, sum, 2, 4);
    float inv = 1.f / sum;
#pragma unroll
    for (int j = 0; j < 16; j++) acc[j] *= inv;

    float o[16];
#pragma unroll
    for (int j = 0; j < 16; j++) o[j] = 0.f;
    int e0 = qd << 4;
#pragma unroll
    for (int tq = 0; tq < 4; tq++) {
#pragma unroll
        for (int j2 = 0; j2 < 16; j2++) {
            float a = __shfl_sync(0xffffffffu, acc[j2], tq, 4);
            const float* vr = &V[tq * 16 + j2][e0];
            float4 v0 = *(const float4*)(vr + 0);
            float4 v1 = *(const float4*)(vr + 4);
            float4 v2 = *(const float4*)(vr + 8);
            float4 v3 = *(const float4*)(vr + 12);
            o[0]  = fmaf(a, v0.x, o[0]);  o[1]  = fmaf(a, v0.y, o[1]);
            o[2]  = fmaf(a, v0.z, o[2]);  o[3]  = fmaf(a, v0.w, o[3]);
            o[4]  = fmaf(a, v1.x, o[4]);  o[5]  = fmaf(a, v1.y, o[5]);
            o[6]  = fmaf(a, v1.z, o[6]);  o[7]  = fmaf(a, v1.w, o[7]);
            o[8]  = fmaf(a, v2.x, o[8]);  o[9]  = fmaf(a, v2.y, o[9]);
            o[10] = fmaf(a, v2.z, o[10]); o[11] = fmaf(a, v2.w, o[11]);
            o[12] = fmaf(a, v3.x, o[12]); o[13] = fmaf(a, v3.y, o[13]);
            o[14] = fmaf(a, v3.z, o[14]); o[15] = fmaf(a, v3.w, o[15]);
        }
    }

    __half2* op = (__half2*)(ATT + (size_t)(n * 64 + s) * 512 + (size_t)h * 64 + e0);
#pragma unroll
    for (int j = 0; j < 8; j++)
        op[j] = __floats2half2_rn(o[2 * j], o[2 * j + 1]);
}

// ---------------------------------------------------------------------------
// LayerNorm: fp32 in; out fp16 (GEMM operand) or fp32 (pool input)
// ---------------------------------------------------------------------------
__global__ void k_ln(const float* __restrict__ in, const float* __restrict__ gam,
                     const float* __restrict__ bet,
                     float* __restrict__ outf, __half* __restrict__ outh, int half_out) {
    int r = blockIdx.x;
    if (r >= g_maxn * 64) return;
    int t = threadIdx.x;
    float4 v = ((const float4*)(in + (size_t)r * 512))[t];
    float s  = v.x + v.y + v.z + v.w;
    float ss = fmaf(v.x, v.x, fmaf(v.y, v.y, fmaf(v.z, v.z, v.w * v.w)));
#pragma unroll
    for (int o = 16; o; o >>= 1) {
        s  += __shfl_xor_sync(0xffffffffu, s,  o);
        ss += __shfl_xor_sync(0xffffffffu, ss, o);
    }
    __shared__ float sh[8];
    if ((t & 31) == 0) { sh[t >> 5] = s; sh[4 + (t >> 5)] = ss; }
    __syncthreads();
    s  = sh[0] + sh[1] + sh[2] + sh[3];
    ss = sh[4] + sh[5] + sh[6] + sh[7];
    float mean = s * (1.f / 512.f);
    float var  = ss * (1.f / 512.f) - mean * mean;
    float inv  = rsqrtf(var + 1e-5f);
    float4 g4 = ((const float4*)gam)[t];
    float4 b4 = ((const float4*)bet)[t];
    float4 o4;
    o4.x = (v.x - mean) * inv * g4.x + b4.x;
    o4.y = (v.y - mean) * inv * g4.y + b4.y;
    o4.z = (v.z - mean) * inv * g4.z + b4.z;
    o4.w = (v.w - mean) * inv * g4.w + b4.w;
    if (half_out) {
        __half2* d = (__half2*)(outh + (size_t)r * 512 + t * 4);
        d[0] = __floats2half2_rn(o4.x, o4.y);
        d[1] = __floats2half2_rn(o4.z, o4.w);
    } else {
        ((float4*)(outf + (size_t)r * 512))[t] = o4;
    }
}

__global__ void k_pool(const float* __restrict__ Xf, float* __restrict__ out) {
    int g = blockIdx.x;
    int d = threadIdx.x;
    int mx = g_maxn;
    const float* p = Xf + (size_t)g * 512 + d;
    const size_t stride = 64 * 512;
    float s0 = 0.f, s1 = 0.f, s2 = 0.f, s3 = 0.f;
    int n = 0;
    for (; n + 4 <= mx; n += 4) {
        s0 += p[(size_t)(n + 0) * stride];
        s1 += p[(size_t)(n + 1) * stride];
        s2 += p[(size_t)(n + 2) * stride];
        s3 += p[(size_t)(n + 3) * stride];
    }
    for (; n < mx; n++) s0 += p[(size_t)n * stride];
    out[g * 512 + d] = (s0 + s1 + s2 + s3) / (float)mx;
}

// ---------------------------------------------------------------------------
// Launch
// ---------------------------------------------------------------------------
extern "C" void kernel_launch(void* const* d_in, const int* in_sizes, int n_in,
                              void* d_out, int out_size) {
    const float* emb  = (const float*)d_in[0];
    const int*   sidx = (const int*)  d_in[1];
    const float* W_in = (const float*)d_in[2];
    const float* b_in = (const float*)d_in[3];
    const float* W_o  = (const float*)d_in[4];
    const float* b_o  = (const float*)d_in[5];
    const float* ln1g = (const float*)d_in[6];
    const float* ln1b = (const float*)d_in[7];
    const float* W1   = (const float*)d_in[8];
    const float* b1   = (const float*)d_in[9];
    const float* W2   = (const float*)d_in[10];
    const float* b2   = (const float*)d_in[11];
    const float* ln2g = (const float*)d_in[12];
    const float* ln2b = (const float*)d_in[13];
    float* out = (float*)d_out;
    (void)n_in; (void)out_size;

    int N = in_sizes[0] / 512;

    __half *pXh, *pATTh, *pY1h, *pHIDh, *pWh;
    float *pQKV, *pTMP;
    cudaGetSymbolAddress((void**)&pXh,   g_Xh);
    cudaGetSymbolAddress((void**)&pQKV,  g_QKV);
    cudaGetSymbolAddress((void**)&pATTh, g_ATTh);
    cudaGetSymbolAddress((void**)&pTMP,  g_TMP);
    cudaGetSymbolAddress((void**)&pY1h,  g_Y1h);
    cudaGetSymbolAddress((void**)&pHIDh, g_HIDh);
    cudaGetSymbolAddress((void**)&pWh,   g_Wh);

    __half* hWin = pWh;                 // 786432
    __half* hWo  = pWh + 786432;        // 262144
    __half* hW1  = pWh + 1048576;       // 524288
    __half* hW2  = pWh + 1572864;       // 524288

    cudaFuncSetAttribute(k_tgemm, cudaFuncAttributeMaxDynamicSharedMemorySize,
                         (int)TG_SMEM_BYTES);

    const int GY = ROWS_CAP / 128;     // 1280 row tiles (beyond-M blocks exit)

    k_meta<<<1, 128>>>(sidx, N);
    k_zeropad<<<64, 256>>>();
    k_scatter<<<N, 128>>>(emb, sidx);
    k_cvtw<<<768, 256>>>(W_in, hWin, 196608);
    k_cvtw<<<256, 256>>>(W_o,  hWo,   65536);
    k_cvtw<<<512, 256>>>(W1,   hW1,  131072);
    k_cvtw<<<512, 256>>>(W2,   hW2,  131072);

    // QKV = X @ W_in^T + b_in                      [M, 1536] fp32 out
    k_tgemm<<<dim3(12, GY), 256, TG_SMEM_BYTES>>>(pXh, hWin, b_in, nullptr,
                                                  pQKV, 1536, 512, 0, 0);

    // attention                                     -> ATT [M, 512] fp16
    k_attn<<<dim3(CAP, 8), 256>>>(pQKV, pATTh);

    // TMP = ATT @ W_o^T + b_o + X                  [M, 512] fp32 out
    k_tgemm<<<dim3(4, GY), 256, TG_SMEM_BYTES>>>(pATTh, hWo, b_o, pXh,
                                                 pTMP, 512, 512, 0, 0);

    // Y1 = LN1(TMP) -> fp16 (GEMM A-operand + residual)
    k_ln<<<ROWS_CAP, 128>>>(pTMP, ln1g, ln1b, nullptr, pY1h, 1);

    // HID = relu(Y1 @ W1^T + b1)                   [M, 1024] fp16 out
    k_tgemm<<<dim3(8, GY), 256, TG_SMEM_BYTES>>>(pY1h, hW1, b1, nullptr,
                                                 pHIDh, 1024, 512, 1, 1);

    // TMP = HID @ W2^T + b2 + Y1                   [M, 512] fp32 out
    k_tgemm<<<dim3(4, GY), 256, TG_SMEM_BYTES>>>(pHIDh, hW2, b2, pY1h,
                                                 pTMP, 512, 1024, 0, 0);

    // X2 = LN2(TMP) -> fp32 into QKV buffer (pool input)
    k_ln<<<ROWS_CAP, 128>>>(pTMP, ln2g, ln2b, pQKV, nullptr, 0);

    k_pool<<<64, 512>>>(pQKV, out);
}

// round 11
// speedup vs baseline: 3.6354x; 1.7383x over previous
#include <cuda_runtime.h>
#include <cuda_fp16.h>
#include <math.h>
#include <stdint.h>

// ---------------------------------------------------------------------------
// Problem: D=512, H=8 (e=64), B=64 studies, N=131072 cells.
// Padded layout: row r = n*64 + g. max_n data-dependent; CAP upper bound.
// fp16 datapath (11-bit mantissa == tf32): all GEMM/attention operands are
// fp16-rounded at the producer; mma.sync m16n8k16 f16 with fp32 accumulate.
// ---------------------------------------------------------------------------
#define CAP       2560
#define ROWS_CAP  (CAP * 64)   // 163840

__device__ int g_maxn;
__device__ int g_starts[65];
__device__ int g_counts[64];

__device__ __align__(128) __half g_Xh  [(size_t)ROWS_CAP * 512];   // X (fp16)
__device__ __align__(128) __half g_QKVh[(size_t)ROWS_CAP * 1536];  // QKV fp16
__device__ __align__(128) __half g_ATTh[(size_t)ROWS_CAP * 512];   // attn out
__device__ float  g_TMP[(size_t)ROWS_CAP * 512];                   // fp32
__device__ __align__(128) __half g_Y1h [(size_t)ROWS_CAP * 512];   // LN1 out
__device__ __align__(128) __half g_HIDh[(size_t)ROWS_CAP * 1024];  // FF hidden
__device__ __align__(128) __half g_Wh  [2097152];  // fp16 W_in | W_o | W1 | W2

// ---------------------------------------------------------------------------
// Meta / zeropad / scatter / weight conversion
// ---------------------------------------------------------------------------
__global__ void k_meta(const int* __restrict__ idx, int N) {
    __shared__ int st[65];
    __shared__ int smax;
    int t = threadIdx.x;
    if (t == 0) smax = 0;
    if (t <= 64) {
        if (t == 64) st[64] = N;
        else {
            int lo = 0, hi = N;
            while (lo < hi) { int mid = (lo + hi) >> 1; if (idx[mid] < t) lo = mid + 1; else hi = mid; }
            st[t] = lo;
        }
    }
    __syncthreads();
    if (t < 64) {
        int c = st[t + 1] - st[t];
        g_starts[t] = st[t];
        g_counts[t] = c;
        atomicMax(&smax, c);
    }
    if (t == 64) g_starts[64] = N;
    __syncthreads();
    if (t == 0) g_maxn = (smax < CAP) ? smax : CAP;
}

__global__ void k_zeropad() {
    int g = blockIdx.x;
    int c0 = g_counts[g];
    int rows = g_maxn - c0;
    if (rows <= 0) return;
    uint4 z = make_uint4(0u, 0u, 0u, 0u);
    for (int w = threadIdx.x; w < rows * 64; w += 256) {
        int n = c0 + (w >> 6);
        int j = w & 63;
        ((uint4*)(g_Xh + (size_t)((n << 6) + g) * 512))[j] = z;
    }
}

__global__ void k_scatter(const float* __restrict__ emb, const int* __restrict__ idx) {
    int i = blockIdx.x;
    int g = idx[i];
    int n = i - g_starts[g];
    int t = threadIdx.x;
    float4 v = ((const float4*)(emb + (size_t)i * 512))[t];
    __half2* d = (__half2*)(g_Xh + (size_t)(n * 64 + g) * 512 + t * 4);
    d[0] = __floats2half2_rn(v.x, v.y);
    d[1] = __floats2half2_rn(v.z, v.w);
}

__global__ void k_cvtw(const float* __restrict__ s, __half* __restrict__ d, int n4) {
    int i = blockIdx.x * 256 + threadIdx.x;
    if (i >= n4) return;
    float4 v = ((const float4*)s)[i];
    __half2* p = (__half2*)(d + (size_t)i * 4);
    p[0] = __floats2half2_rn(v.x, v.y);
    p[1] = __floats2half2_rn(v.z, v.w);
}

// ---------------------------------------------------------------------------
// fp16 mma helpers
// ---------------------------------------------------------------------------
__device__ __forceinline__ void mma_f16(float c[4],
                                        uint32_t a0, uint32_t a1, uint32_t a2, uint32_t a3,
                                        uint32_t b0, uint32_t b1) {
    asm volatile(
        "mma.sync.aligned.m16n8k16.row.col.f32.f16.f16.f32 "
        "{%0,%1,%2,%3}, {%4,%5,%6,%7}, {%8,%9}, {%0,%1,%2,%3};"
        : "+f"(c[0]), "+f"(c[1]), "+f"(c[2]), "+f"(c[3])
        : "r"(a0), "r"(a1), "r"(a2), "r"(a3), "r"(b0), "r"(b1));
}
#define LDSM4(f, a) \
    asm volatile("ldmatrix.sync.aligned.m8n8.x4.shared.b16 {%0,%1,%2,%3}, [%4];" \
                 : "=r"((f)[0]), "=r"((f)[1]), "=r"((f)[2]), "=r"((f)[3]) : "r"(a))
#define LDSM4T(f, a) \
    asm volatile("ldmatrix.sync.aligned.m8n8.x4.trans.shared.b16 {%0,%1,%2,%3}, [%4];" \
                 : "=r"((f)[0]), "=r"((f)[1]), "=r"((f)[2]), "=r"((f)[3]) : "r"(a))

__device__ __forceinline__ uint32_t packh2(float a, float b) {
    __half2 h = __floats2half2_rn(a, b);
    return *(uint32_t*)&h;
}

// ---------------------------------------------------------------------------
// fp16 tensor-core GEMM (proven R10): C = A*Bw^T + bias (+resid)(relu)
// BM=BN=128, BK=32 halves. 8 warps, warp tile 64x32, 3-stage cp.async ring.
// ---------------------------------------------------------------------------
#define SROW_H 40
#define A_BYTES (128u * SROW_H * 2u)    // 10240
#define STAGE_B (2u * A_BYTES)          // 20480
#define TG_SMEM_BYTES (3u * STAGE_B)    // 61440

__global__ __launch_bounds__(256, 2)
void k_tgemm(const __half* __restrict__ A, const __half* __restrict__ Bw,
             const float* __restrict__ bias, const __half* __restrict__ resid,
             void* __restrict__ Cv, int Ncols, int K, int relu, int out_half)
{
    int M = g_maxn * 64;
    int row0 = blockIdx.y * 128;
    if (row0 >= M) return;
    int col0 = blockIdx.x * 128;

    int tid  = threadIdx.x;
    int lane = tid & 31;
    int wid  = tid >> 5;
    int wm   = wid & 1;
    int wn   = wid >> 1;
    int g    = lane >> 2;
    int tg   = lane & 3;

    extern __shared__ uint32_t sm[];
    uint32_t smb = (uint32_t)__cvta_generic_to_shared(sm);

    const __half* Abase = A  + (size_t)row0 * K;
    const __half* Bbase = Bw + (size_t)col0 * K;

    int srow = tid >> 2;
    int sc   = tid & 3;

    uint32_t rowA = (uint32_t)(((wm * 64 + (lane & 15)) * SROW_H + (lane >> 4) * 8) * 2);
    uint32_t rowB = (uint32_t)(((wn * 32 + (lane & 7) + ((lane >> 3) & 1) * 8) * SROW_H
                                + (lane >> 4) * 8) * 2);

    float c[4][4][4];
#pragma unroll
    for (int i = 0; i < 4; i++)
#pragma unroll
        for (int j = 0; j < 4; j++)
#pragma unroll
            for (int k = 0; k < 4; k++) c[i][j][k] = 0.f;

    const int KT = K >> 5;

#define STAGE(kt_)  do {                                                          \
        int _kt = (kt_);                                                          \
        uint32_t _sb = smb + (uint32_t)(_kt % 3) * STAGE_B;                       \
        int _ko = _kt * 32 + sc * 8;                                              \
        _Pragma("unroll")                                                         \
        for (int _i = 0; _i < 2; _i++) {                                          \
            int _row = srow + 64 * _i;                                            \
            uint32_t _d = _sb + (uint32_t)((_row * SROW_H + sc * 8) * 2);         \
            int _ok = (row0 + _row) < M;                                          \
            const __half* _sa = Abase + (size_t)(_ok ? _row : 0) * K + _ko;       \
            int _sz = _ok ? 16 : 0;                                               \
            asm volatile("cp.async.cg.shared.global [%0], [%1], 16, %2;"          \
                         :: "r"(_d), "l"(_sa), "r"(_sz));                         \
            uint32_t _d2 = _d + A_BYTES;                                          \
            const __half* _sb2 = Bbase + (size_t)_row * K + _ko;                  \
            asm volatile("cp.async.cg.shared.global [%0], [%1], 16;"              \
                         :: "r"(_d2), "l"(_sb2));                                 \
        }                                                                         \
        asm volatile("cp.async.commit_group;");                                   \
    } while (0)

    STAGE(0);
    STAGE(1);

    uint32_t fa[2][4][4], fb[2][2][4];

    for (int kt = 0; kt < KT; kt++) {
        if (kt + 1 < KT) { asm volatile("cp.async.wait_group 1;"); }
        else             { asm volatile("cp.async.wait_group 0;"); }
        __syncthreads();
        if (kt + 2 < KT) STAGE(kt + 2);

        uint32_t aB = smb + (uint32_t)(kt % 3) * STAGE_B + rowA;
        uint32_t bB = smb + (uint32_t)(kt % 3) * STAGE_B + A_BYTES + rowB;

#pragma unroll
        for (int mt = 0; mt < 4; mt++)
            LDSM4(fa[0][mt], aB + (uint32_t)(mt * 16 * SROW_H * 2));
#pragma unroll
        for (int p = 0; p < 2; p++)
            LDSM4(fb[0][p], bB + (uint32_t)(p * 16 * SROW_H * 2));

#pragma unroll
        for (int kk = 0; kk < 2; kk++) {
            const int cb = kk & 1, nb = cb ^ 1;
            if (kk < 1) {
#pragma unroll
                for (int mt = 0; mt < 4; mt++)
                    LDSM4(fa[nb][mt], aB + (uint32_t)(mt * 16 * SROW_H * 2 + 32));
#pragma unroll
                for (int p = 0; p < 2; p++)
                    LDSM4(fb[nb][p], bB + (uint32_t)(p * 16 * SROW_H * 2 + 32));
            }
#pragma unroll
            for (int p = 0; p < 2; p++)
#pragma unroll
                for (int mt = 0; mt < 4; mt++) {
                    mma_f16(c[mt][2 * p],
                            fa[cb][mt][0], fa[cb][mt][1], fa[cb][mt][2], fa[cb][mt][3],
                            fb[cb][p][0], fb[cb][p][2]);
                    mma_f16(c[mt][2 * p + 1],
                            fa[cb][mt][0], fa[cb][mt][1], fa[cb][mt][2], fa[cb][mt][3],
                            fb[cb][p][1], fb[cb][p][3]);
                }
        }
    }

    float*  Cf = (float*)Cv;
    __half* Ch = (__half*)Cv;
#pragma unroll
    for (int mt = 0; mt < 4; mt++) {
        int r0 = row0 + wm * 64 + mt * 16 + g;
        int r1 = r0 + 8;
#pragma unroll
        for (int nt = 0; nt < 4; nt++) {
            int cc = col0 + wn * 32 + nt * 8 + 2 * tg;
            float2 bv = *(const float2*)(bias + cc);
#pragma unroll
            for (int hrow = 0; hrow < 2; hrow++) {
                int r = hrow ? r1 : r0;
                if (r >= M) continue;
                float o0 = c[mt][nt][2 * hrow + 0] + bv.x;
                float o1 = c[mt][nt][2 * hrow + 1] + bv.y;
                if (resid) {
                    __half2 rv = *(const __half2*)(resid + (size_t)r * Ncols + cc);
                    float2 rf = __half22float2(rv);
                    o0 += rf.x; o1 += rf.y;
                }
                if (relu) { o0 = fmaxf(o0, 0.f); o1 = fmaxf(o1, 0.f); }
                if (out_half) {
                    *(__half2*)(Ch + (size_t)r * Ncols + cc) = __floats2half2_rn(o0, o1);
                } else {
                    *(float2*)(Cf + (size_t)r * Ncols + cc) = make_float2(o0, o1);
                }
            }
        }
    }
#undef STAGE
}

// ---------------------------------------------------------------------------
// Tensor-core attention. One block (128 thr, 4 warps) per (position n, head h).
// Warp w owns query rows s in [16w, 16w+16).
// S = Q K^T via m16n8k16 (A: Q[s][e]; B: K[t][e] == col-major B, non-trans).
// Masked softmax on C fragments (xor-1/xor-2 within 4-lane row groups).
// P fragments re-packed from S registers per-lane (C-layout -> A-layout).
// O = P V via m16n8k16 (B: V[t][e] through ldmatrix.trans -> [e][t]).
// ---------------------------------------------------------------------------
__global__ __launch_bounds__(128)
void k_attn(const __half* __restrict__ QKVh, __half* __restrict__ ATT) {
    int n = blockIdx.x;
    if (n >= g_maxn) return;
    int h = blockIdx.y;

    __shared__ __half sQ[64 * 72];
    __shared__ __half sK[64 * 72];
    __shared__ __half sV[64 * 72];
    __shared__ int scnt[64];

    int tid  = threadIdx.x;
    int lane = tid & 31;
    int w    = tid >> 5;

    if (tid < 64) scnt[tid] = g_counts[tid];

    // Load Q/K/V rows for this (n, h): 64 rows x 64 halves each matrix.
    const __half* base = QKVh + (size_t)n * 64 * 1536 + (size_t)h * 64;
    for (int i = tid; i < 1536; i += 128) {
        int m   = i >> 9;          // 0=Q 1=K 2=V
        int rem = i & 511;
        int row = rem >> 3;
        int c8  = rem & 7;
        const uint4* src = (const uint4*)(base + (size_t)row * 1536 + m * 512 + c8 * 8);
        __half* dstm = (m == 0) ? sQ : ((m == 1) ? sK : sV);
        *(uint4*)(dstm + row * 72 + c8 * 8) = *src;
    }
    __syncthreads();

    uint32_t qb = (uint32_t)__cvta_generic_to_shared(sQ);
    uint32_t kb = (uint32_t)__cvta_generic_to_shared(sK);
    uint32_t vbs = (uint32_t)__cvta_generic_to_shared(sV);

    int s0 = w * 16;
    int c2 = 2 * (lane & 3);

    // ldmatrix lane-address components
    int aRow = s0 + (lane & 7) + ((lane & 8) ? 8 : 0);      // A tiles: r / r+8
    int aCol = ((lane & 16) ? 8 : 0);                       // k halves
    int bRow = (lane & 7) + ((lane & 16) ? 8 : 0);          // K tiles: n / n+8
    int bCol = ((lane & 8) ? 8 : 0);                        // k halves
    int vRow = (lane & 7) + ((lane & 8) ? 8 : 0);           // V tiles: k / k+8
    int vCol = ((lane & 16) ? 8 : 0);                       // n(e) halves

    // ---- S = Q K^T ----
    float cS[8][4];
#pragma unroll
    for (int i = 0; i < 8; i++)
#pragma unroll
        for (int j = 0; j < 4; j++) cS[i][j] = 0.f;

#pragma unroll
    for (int ke = 0; ke < 4; ke++) {
        uint32_t a[4];
        LDSM4(a, qb + (uint32_t)((aRow * 72 + ke * 16 + aCol) * 2));
#pragma unroll
        for (int q = 0; q < 4; q++) {
            uint32_t b[4];
            LDSM4(b, kb + (uint32_t)(((16 * q + bRow) * 72 + ke * 16 + bCol) * 2));
            mma_f16(cS[2 * q],     a[0], a[1], a[2], a[3], b[0], b[1]);
            mma_f16(cS[2 * q + 1], a[0], a[1], a[2], a[3], b[2], b[3]);
        }
    }

    // ---- masked softmax over t (64 keys), rows r and r+8 per lane ----
#pragma unroll
    for (int hrow = 0; hrow < 2; hrow++) {
        int o = 2 * hrow;
        float mx = -1e30f;
#pragma unroll
        for (int nt = 0; nt < 8; nt++) {
#pragma unroll
            for (int e = 0; e < 2; e++) {
                int t = nt * 8 + c2 + e;
                float v = cS[nt][o + e] * 0.125f;
                if (scnt[t] <= n) v = -1e30f;
                cS[nt][o + e] = v;
                mx = fmaxf(mx, v);
            }
        }
        mx = fmaxf(mx, __shfl_xor_sync(0xffffffffu, mx, 1));
        mx = fmaxf(mx, __shfl_xor_sync(0xffffffffu, mx, 2));
        float sum = 0.f;
#pragma unroll
        for (int nt = 0; nt < 8; nt++) {
#pragma unroll
            for (int e = 0; e < 2; e++) {
                float p = __expf(cS[nt][o + e] - mx);
                cS[nt][o + e] = p;
                sum += p;
            }
        }
        sum += __shfl_xor_sync(0xffffffffu, sum, 1);
        sum += __shfl_xor_sync(0xffffffffu, sum, 2);
        float inv = 1.f / sum;
#pragma unroll
        for (int nt = 0; nt < 8; nt++) {
            cS[nt][o + 0] *= inv;
            cS[nt][o + 1] *= inv;
        }
    }

    // ---- P fragments (C-layout -> A-layout, zero shuffles) ----
    uint32_t pa[4][4];
#pragma unroll
    for (int j = 0; j < 4; j++) {
        pa[j][0] = packh2(cS[2 * j][0],     cS[2 * j][1]);
        pa[j][1] = packh2(cS[2 * j][2],     cS[2 * j][3]);
        pa[j][2] = packh2(cS[2 * j + 1][0], cS[2 * j + 1][1]);
        pa[j][3] = packh2(cS[2 * j + 1][2], cS[2 * j + 1][3]);
    }

    // ---- O = P V ----
    float cO[8][4];
#pragma unroll
    for (int i = 0; i < 8; i++)
#pragma unroll
        for (int j = 0; j < 4; j++) cO[i][j] = 0.f;

#pragma unroll
    for (int j = 0; j < 4; j++) {        // k-tiles over t
#pragma unroll
        for (int p = 0; p < 4; p++) {    // e 16-pairs
            uint32_t b[4];
            LDSM4T(b, vbs + (uint32_t)(((16 * j + vRow) * 72 + p * 16 + vCol) * 2));
            mma_f16(cO[2 * p],     pa[j][0], pa[j][1], pa[j][2], pa[j][3], b[0], b[1]);
            mma_f16(cO[2 * p + 1], pa[j][0], pa[j][1], pa[j][2], pa[j][3], b[2], b[3]);
        }
    }

    // ---- store O (fp16) ----
    int r = s0 + (lane >> 2);
#pragma unroll
    for (int nt = 0; nt < 8; nt++) {
        int col = h * 64 + nt * 8 + c2;
        *(__half2*)(ATT + (size_t)(n * 64 + r) * 512 + col)       = *(__half2*)&(uint32_t){packh2(cO[nt][0], cO[nt][1])};
        *(__half2*)(ATT + (size_t)(n * 64 + r + 8) * 512 + col)   = *(__half2*)&(uint32_t){packh2(cO[nt][2], cO[nt][3])};
    }
}

// ---------------------------------------------------------------------------
// LayerNorm: fp32 in; out fp16 (GEMM operand) or fp32 (pool input)
// ---------------------------------------------------------------------------
__global__ void k_ln(const float* __restrict__ in, const float* __restrict__ gam,
                     const float* __restrict__ bet,
                     float* __restrict__ outf, __half* __restrict__ outh, int half_out) {
    int r = blockIdx.x;
    if (r >= g_maxn * 64) return;
    int t = threadIdx.x;
    float4 v = ((const float4*)(in + (size_t)r * 512))[t];
    float s  = v.x + v.y + v.z + v.w;
    float ss = fmaf(v.x, v.x, fmaf(v.y, v.y, fmaf(v.z, v.z, v.w * v.w)));
#pragma unroll
    for (int o = 16; o; o >>= 1) {
        s  += __shfl_xor_sync(0xffffffffu, s,  o);
        ss += __shfl_xor_sync(0xffffffffu, ss, o);
    }
    __shared__ float sh[8];
    if ((t & 31) == 0) { sh[t >> 5] = s; sh[4 + (t >> 5)] = ss; }
    __syncthreads();
    s  = sh[0] + sh[1] + sh[2] + sh[3];
    ss = sh[4] + sh[5] + sh[6] + sh[7];
    float mean = s * (1.f / 512.f);
    float var  = ss * (1.f / 512.f) - mean * mean;
    float inv  = rsqrtf(var + 1e-5f);
    float4 g4 = ((const float4*)gam)[t];
    float4 b4 = ((const float4*)bet)[t];
    float4 o4;
    o4.x = (v.x - mean) * inv * g4.x + b4.x;
    o4.y = (v.y - mean) * inv * g4.y + b4.y;
    o4.z = (v.z - mean) * inv * g4.z + b4.z;
    o4.w = (v.w - mean) * inv * g4.w + b4.w;
    if (half_out) {
        __half2* d = (__half2*)(outh + (size_t)r * 512 + t * 4);
        d[0] = __floats2half2_rn(o4.x, o4.y);
        d[1] = __floats2half2_rn(o4.z, o4.w);
    } else {
        ((float4*)(outf + (size_t)r * 512))[t] = o4;
    }
}

__global__ void k_pool(const float* __restrict__ Xf, float* __restrict__ out) {
    int g = blockIdx.x;
    int d = threadIdx.x;
    int mx = g_maxn;
    const float* p = Xf + (size_t)g * 512 + d;
    const size_t stride = 64 * 512;
    float s0 = 0.f, s1 = 0.f, s2 = 0.f, s3 = 0.f;
    int n = 0;
    for (; n + 4 <= mx; n += 4) {
        s0 += p[(size_t)(n + 0) * stride];
        s1 += p[(size_t)(n + 1) * stride];
        s2 += p[(size_t)(n + 2) * stride];
        s3 += p[(size_t)(n + 3) * stride];
    }
    for (; n < mx; n++) s0 += p[(size_t)n * stride];
    out[g * 512 + d] = (s0 + s1 + s2 + s3) / (float)mx;
}

// ---------------------------------------------------------------------------
// Launch
// ---------------------------------------------------------------------------
extern "C" void kernel_launch(void* const* d_in, const int* in_sizes, int n_in,
                              void* d_out, int out_size) {
    const float* emb  = (const float*)d_in[0];
    const int*   sidx = (const int*)  d_in[1];
    const float* W_in = (const float*)d_in[2];
    const float* b_in = (const float*)d_in[3];
    const float* W_o  = (const float*)d_in[4];
    const float* b_o  = (const float*)d_in[5];
    const float* ln1g = (const float*)d_in[6];
    const float* ln1b = (const float*)d_in[7];
    const float* W1   = (const float*)d_in[8];
    const float* b1   = (const float*)d_in[9];
    const float* W2   = (const float*)d_in[10];
    const float* b2   = (const float*)d_in[11];
    const float* ln2g = (const float*)d_in[12];
    const float* ln2b = (const float*)d_in[13];
    float* out = (float*)d_out;
    (void)n_in; (void)out_size;

    int N = in_sizes[0] / 512;

    __half *pXh, *pQKVh, *pATTh, *pY1h, *pHIDh, *pWh;
    float *pTMP;
    cudaGetSymbolAddress((void**)&pXh,   g_Xh);
    cudaGetSymbolAddress((void**)&pQKVh, g_QKVh);
    cudaGetSymbolAddress((void**)&pATTh, g_ATTh);
    cudaGetSymbolAddress((void**)&pTMP,  g_TMP);
    cudaGetSymbolAddress((void**)&pY1h,  g_Y1h);
    cudaGetSymbolAddress((void**)&pHIDh, g_HIDh);
    cudaGetSymbolAddress((void**)&pWh,   g_Wh);

    __half* hWin = pWh;                 // 786432
    __half* hWo  = pWh + 786432;        // 262144
    __half* hW1  = pWh + 1048576;       // 524288
    __half* hW2  = pWh + 1572864;       // 524288

    cudaFuncSetAttribute(k_tgemm, cudaFuncAttributeMaxDynamicSharedMemorySize,
                         (int)TG_SMEM_BYTES);

    const int GY = ROWS_CAP / 128;

    k_meta<<<1, 128>>>(sidx, N);
    k_zeropad<<<64, 256>>>();
    k_scatter<<<N, 128>>>(emb, sidx);
    k_cvtw<<<768, 256>>>(W_in, hWin, 196608);
    k_cvtw<<<256, 256>>>(W_o,  hWo,   65536);
    k_cvtw<<<512, 256>>>(W1,   hW1,  131072);
    k_cvtw<<<512, 256>>>(W2,   hW2,  131072);

    // QKV = X @ W_in^T + b_in                      [M, 1536] fp16 out
    k_tgemm<<<dim3(12, GY), 256, TG_SMEM_BYTES>>>(pXh, hWin, b_in, nullptr,
                                                  pQKVh, 1536, 512, 0, 1);

    // tensor-core attention                         -> ATT [M, 512] fp16
    k_attn<<<dim3(CAP, 8), 128>>>(pQKVh, pATTh);

    // TMP = ATT @ W_o^T + b_o + X                  [M, 512] fp32 out
    k_tgemm<<<dim3(4, GY), 256, TG_SMEM_BYTES>>>(pATTh, hWo, b_o, pXh,
                                                 pTMP, 512, 512, 0, 0);

    // Y1 = LN1(TMP) -> fp16
    k_ln<<<ROWS_CAP, 128>>>(pTMP, ln1g, ln1b, nullptr, pY1h, 1);

    // HID = relu(Y1 @ W1^T + b1)                   [M, 1024] fp16 out
    k_tgemm<<<dim3(8, GY), 256, TG_SMEM_BYTES>>>(pY1h, hW1, b1, nullptr,
                                                 pHIDh, 1024, 512, 1, 1);

    // TMP = HID @ W2^T + b2 + Y1                   [M, 512] fp32 out
    k_tgemm<<<dim3(4, GY), 256, TG_SMEM_BYTES>>>(pHIDh, hW2, b2, pY1h,
                                                 pTMP, 512, 1024, 0, 0);

    // X2 = LN2(TMP) -> fp32 in-place (pool input)
    k_ln<<<ROWS_CAP, 128>>>(pTMP, ln2g, ln2b, pTMP, nullptr, 0);

    k_pool<<<64, 512>>>(pTMP, out);
}

// round 12
// speedup vs baseline: 4.0142x; 1.1042x over previous
#include <cuda_runtime.h>
#include <cuda_fp16.h>
#include <math.h>
#include <stdint.h>

// ---------------------------------------------------------------------------
// Problem: D=512, H=8 (e=64), B=64 studies, N=131072 cells.
// Padded layout: row r = n*64 + g. max_n data-dependent; CAP upper bound.
// fp16 datapath everywhere except LN stats / softmax / pool accumulation.
// ---------------------------------------------------------------------------
#define CAP       2560
#define ROWS_CAP  (CAP * 64)   // 163840

__device__ int g_maxn;
__device__ int g_starts[65];
__device__ int g_counts[64];

__device__ __align__(128) __half g_Xh  [(size_t)ROWS_CAP * 512];
__device__ __align__(128) __half g_QKVh[(size_t)ROWS_CAP * 1536];
__device__ __align__(128) __half g_ATTh[(size_t)ROWS_CAP * 512];
__device__ __align__(128) __half g_TMPh[(size_t)ROWS_CAP * 512];
__device__ __align__(128) __half g_Y1h [(size_t)ROWS_CAP * 512];
__device__ __align__(128) __half g_HIDh[(size_t)ROWS_CAP * 1024];
__device__ __align__(128) __half g_Wh  [2097152];  // fp16 W_in | W_o | W1 | W2

// ---------------------------------------------------------------------------
// Meta / zeropad / scatter / weight conversion
// ---------------------------------------------------------------------------
__global__ void k_meta(const int* __restrict__ idx, int N) {
    __shared__ int st[65];
    __shared__ int smax;
    int t = threadIdx.x;
    if (t == 0) smax = 0;
    if (t <= 64) {
        if (t == 64) st[64] = N;
        else {
            int lo = 0, hi = N;
            while (lo < hi) { int mid = (lo + hi) >> 1; if (idx[mid] < t) lo = mid + 1; else hi = mid; }
            st[t] = lo;
        }
    }
    __syncthreads();
    if (t < 64) {
        int c = st[t + 1] - st[t];
        g_starts[t] = st[t];
        g_counts[t] = c;
        atomicMax(&smax, c);
    }
    if (t == 64) g_starts[64] = N;
    __syncthreads();
    if (t == 0) g_maxn = (smax < CAP) ? smax : CAP;
}

__global__ void k_zeropad() {
    int g = blockIdx.x;
    int c0 = g_counts[g];
    int rows = g_maxn - c0;
    if (rows <= 0) return;
    uint4 z = make_uint4(0u, 0u, 0u, 0u);
    for (int w = threadIdx.x; w < rows * 64; w += 256) {
        int n = c0 + (w >> 6);
        int j = w & 63;
        ((uint4*)(g_Xh + (size_t)((n << 6) + g) * 512))[j] = z;
    }
}

__global__ void k_scatter(const float* __restrict__ emb, const int* __restrict__ idx) {
    int i = blockIdx.x;
    int g = idx[i];
    int n = i - g_starts[g];
    int t = threadIdx.x;
    float4 v = ((const float4*)(emb + (size_t)i * 512))[t];
    __half2* d = (__half2*)(g_Xh + (size_t)(n * 64 + g) * 512 + t * 4);
    d[0] = __floats2half2_rn(v.x, v.y);
    d[1] = __floats2half2_rn(v.z, v.w);
}

__global__ void k_cvtw(const float* __restrict__ s, __half* __restrict__ d, int n4) {
    int i = blockIdx.x * 256 + threadIdx.x;
    if (i >= n4) return;
    float4 v = ((const float4*)s)[i];
    __half2* p = (__half2*)(d + (size_t)i * 4);
    p[0] = __floats2half2_rn(v.x, v.y);
    p[1] = __floats2half2_rn(v.z, v.w);
}

// ---------------------------------------------------------------------------
// fp16 mma helpers
// ---------------------------------------------------------------------------
__device__ __forceinline__ void mma_f16(float c[4],
                                        uint32_t a0, uint32_t a1, uint32_t a2, uint32_t a3,
                                        uint32_t b0, uint32_t b1) {
    asm volatile(
        "mma.sync.aligned.m16n8k16.row.col.f32.f16.f16.f32 "
        "{%0,%1,%2,%3}, {%4,%5,%6,%7}, {%8,%9}, {%0,%1,%2,%3};"
        : "+f"(c[0]), "+f"(c[1]), "+f"(c[2]), "+f"(c[3])
        : "r"(a0), "r"(a1), "r"(a2), "r"(a3), "r"(b0), "r"(b1));
}
#define LDSM4(f, a) \
    asm volatile("ldmatrix.sync.aligned.m8n8.x4.shared.b16 {%0,%1,%2,%3}, [%4];" \
                 : "=r"((f)[0]), "=r"((f)[1]), "=r"((f)[2]), "=r"((f)[3]) : "r"(a))
#define LDSM4T(f, a) \
    asm volatile("ldmatrix.sync.aligned.m8n8.x4.trans.shared.b16 {%0,%1,%2,%3}, [%4];" \
                 : "=r"((f)[0]), "=r"((f)[1]), "=r"((f)[2]), "=r"((f)[3]) : "r"(a))

__device__ __forceinline__ uint32_t packh2(float a, float b) {
    __half2 h = __floats2half2_rn(a, b);
    return *(uint32_t*)&h;
}

// ---------------------------------------------------------------------------
// fp16 tensor-core GEMM: C = A*Bw^T + bias (+resid fp16)(relu); out fp16.
// BM=BN=128, BK=64 halves (halved barrier count vs BK=32).
// 8 warps, warp tile 64x32 (4x4 m16n8k16, kk=4), 3-stage cp.async ring.
// SROW_H=72 halves (36 words): 4*r mod 32 distinct -> conflict-free LDSM.
// ---------------------------------------------------------------------------
#define SROW_H 72
#define A_BYTES (128u * SROW_H * 2u)    // 18432
#define STAGE_B (2u * A_BYTES)          // 36864
#define TG_SMEM_BYTES (3u * STAGE_B)    // 110592

__global__ __launch_bounds__(256, 2)
void k_tgemm(const __half* __restrict__ A, const __half* __restrict__ Bw,
             const float* __restrict__ bias, const __half* __restrict__ resid,
             __half* __restrict__ C, int Ncols, int K, int relu)
{
    int M = g_maxn * 64;
    int row0 = blockIdx.y * 128;
    if (row0 >= M) return;
    int col0 = blockIdx.x * 128;

    int tid  = threadIdx.x;
    int lane = tid & 31;
    int wid  = tid >> 5;
    int wm   = wid & 1;
    int wn   = wid >> 1;
    int g    = lane >> 2;
    int tg   = lane & 3;

    extern __shared__ uint32_t sm[];
    uint32_t smb = (uint32_t)__cvta_generic_to_shared(sm);

    const __half* Abase = A  + (size_t)row0 * K;
    const __half* Bbase = Bw + (size_t)col0 * K;

    // stage coords: idx = tid + 256*i -> row = idx>>3 (0..127), c8 = idx&7
    int srow = tid >> 3;
    int sc8  = tid & 7;

    // LDSM lane row/pair components (k offset added per kk)
    uint32_t rowA = (uint32_t)((wm * 64 + (lane & 15)) * SROW_H * 2);
    uint32_t kA   = (uint32_t)((lane >> 4) * 16);             // bytes
    uint32_t rowB = (uint32_t)((wn * 32 + (lane & 7) + ((lane >> 3) & 1) * 8) * SROW_H * 2);
    uint32_t kB   = (uint32_t)((lane >> 4) * 16);             // bytes

    float c[4][4][4];
#pragma unroll
    for (int i = 0; i < 4; i++)
#pragma unroll
        for (int j = 0; j < 4; j++)
#pragma unroll
            for (int k = 0; k < 4; k++) c[i][j][k] = 0.f;

    const int KT = K >> 6;   // BK = 64 halves

#define STAGE(kt_)  do {                                                          \
        int _kt = (kt_);                                                          \
        uint32_t _sb = smb + (uint32_t)(_kt % 3) * STAGE_B;                       \
        int _ko = _kt * 64 + sc8 * 8;                                             \
        _Pragma("unroll")                                                         \
        for (int _i = 0; _i < 4; _i++) {                                          \
            int _row = srow + 32 * _i;                                            \
            uint32_t _d = _sb + (uint32_t)((_row * SROW_H + sc8 * 8) * 2);        \
            int _ok = (row0 + _row) < M;                                          \
            const __half* _sa = Abase + (size_t)(_ok ? _row : 0) * K + _ko;       \
            int _sz = _ok ? 16 : 0;                                               \
            asm volatile("cp.async.cg.shared.global [%0], [%1], 16, %2;"          \
                         :: "r"(_d), "l"(_sa), "r"(_sz));                         \
            uint32_t _d2 = _d + A_BYTES;                                          \
            const __half* _sb2 = Bbase + (size_t)_row * K + _ko;                  \
            asm volatile("cp.async.cg.shared.global [%0], [%1], 16;"              \
                         :: "r"(_d2), "l"(_sb2));                                 \
        }                                                                         \
        asm volatile("cp.async.commit_group;");                                   \
    } while (0)

    STAGE(0);
    STAGE(1);

    uint32_t fa[2][4][4], fb[2][2][4];

    for (int kt = 0; kt < KT; kt++) {
        if (kt + 1 < KT) { asm volatile("cp.async.wait_group 1;"); }
        else             { asm volatile("cp.async.wait_group 0;"); }
        __syncthreads();
        if (kt + 2 < KT) STAGE(kt + 2);

        uint32_t aB = smb + (uint32_t)(kt % 3) * STAGE_B;
        uint32_t bB = aB + A_BYTES;

        // fragments for kk=0
#pragma unroll
        for (int mt = 0; mt < 4; mt++)
            LDSM4(fa[0][mt], aB + rowA + (uint32_t)(mt * 16 * SROW_H * 2) + kA);
#pragma unroll
        for (int p = 0; p < 2; p++)
            LDSM4(fb[0][p], bB + rowB + (uint32_t)(p * 16 * SROW_H * 2) + kB);

#pragma unroll
        for (int kk = 0; kk < 4; kk++) {
            const int cb = kk & 1, nb = cb ^ 1;
            if (kk < 3) {
                uint32_t ko = (uint32_t)((kk + 1) * 32);   // 16 halves
#pragma unroll
                for (int mt = 0; mt < 4; mt++)
                    LDSM4(fa[nb][mt], aB + rowA + (uint32_t)(mt * 16 * SROW_H * 2) + kA + ko);
#pragma unroll
                for (int p = 0; p < 2; p++)
                    LDSM4(fb[nb][p], bB + rowB + (uint32_t)(p * 16 * SROW_H * 2) + kB + ko);
            }
#pragma unroll
            for (int p = 0; p < 2; p++)
#pragma unroll
                for (int mt = 0; mt < 4; mt++) {
                    mma_f16(c[mt][2 * p],
                            fa[cb][mt][0], fa[cb][mt][1], fa[cb][mt][2], fa[cb][mt][3],
                            fb[cb][p][0], fb[cb][p][2]);
                    mma_f16(c[mt][2 * p + 1],
                            fa[cb][mt][0], fa[cb][mt][1], fa[cb][mt][2], fa[cb][mt][3],
                            fb[cb][p][1], fb[cb][p][3]);
                }
        }
    }

    // epilogue: bias (+resid fp16) (relu); fp16 out
#pragma unroll
    for (int mt = 0; mt < 4; mt++) {
        int r0 = row0 + wm * 64 + mt * 16 + g;
        int r1 = r0 + 8;
#pragma unroll
        for (int nt = 0; nt < 4; nt++) {
            int cc = col0 + wn * 32 + nt * 8 + 2 * tg;
            float2 bv = *(const float2*)(bias + cc);
#pragma unroll
            for (int hrow = 0; hrow < 2; hrow++) {
                int r = hrow ? r1 : r0;
                if (r >= M) continue;
                float o0 = c[mt][nt][2 * hrow + 0] + bv.x;
                float o1 = c[mt][nt][2 * hrow + 1] + bv.y;
                if (resid) {
                    __half2 rv = *(const __half2*)(resid + (size_t)r * Ncols + cc);
                    float2 rf = __half22float2(rv);
                    o0 += rf.x; o1 += rf.y;
                }
                if (relu) { o0 = fmaxf(o0, 0.f); o1 = fmaxf(o1, 0.f); }
                *(__half2*)(C + (size_t)r * Ncols + cc) = __floats2half2_rn(o0, o1);
            }
        }
    }
#undef STAGE
}

// ---------------------------------------------------------------------------
// Tensor-core attention (proven R11): one block (128 thr) per (n, h).
// ---------------------------------------------------------------------------
__global__ __launch_bounds__(128)
void k_attn(const __half* __restrict__ QKVh, __half* __restrict__ ATT) {
    int n = blockIdx.x;
    if (n >= g_maxn) return;
    int h = blockIdx.y;

    __shared__ __half sQ[64 * 72];
    __shared__ __half sK[64 * 72];
    __shared__ __half sV[64 * 72];
    __shared__ int scnt[64];

    int tid  = threadIdx.x;
    int lane = tid & 31;
    int w    = tid >> 5;

    if (tid < 64) scnt[tid] = g_counts[tid];

    const __half* base = QKVh + (size_t)n * 64 * 1536 + (size_t)h * 64;
    for (int i = tid; i < 1536; i += 128) {
        int m   = i >> 9;
        int rem = i & 511;
        int row = rem >> 3;
        int c8  = rem & 7;
        const uint4* src = (const uint4*)(base + (size_t)row * 1536 + m * 512 + c8 * 8);
        __half* dstm = (m == 0) ? sQ : ((m == 1) ? sK : sV);
        *(uint4*)(dstm + row * 72 + c8 * 8) = *src;
    }
    __syncthreads();

    uint32_t qb  = (uint32_t)__cvta_generic_to_shared(sQ);
    uint32_t kb  = (uint32_t)__cvta_generic_to_shared(sK);
    uint32_t vbs = (uint32_t)__cvta_generic_to_shared(sV);

    int s0 = w * 16;
    int c2 = 2 * (lane & 3);

    int aRow = s0 + (lane & 7) + ((lane & 8) ? 8 : 0);
    int aCol = ((lane & 16) ? 8 : 0);
    int bRow = (lane & 7) + ((lane & 16) ? 8 : 0);
    int bCol = ((lane & 8) ? 8 : 0);
    int vRow = (lane & 7) + ((lane & 8) ? 8 : 0);
    int vCol = ((lane & 16) ? 8 : 0);

    float cS[8][4];
#pragma unroll
    for (int i = 0; i < 8; i++)
#pragma unroll
        for (int j = 0; j < 4; j++) cS[i][j] = 0.f;

#pragma unroll
    for (int ke = 0; ke < 4; ke++) {
        uint32_t a[4];
        LDSM4(a, qb + (uint32_t)((aRow * 72 + ke * 16 + aCol) * 2));
#pragma unroll
        for (int q = 0; q < 4; q++) {
            uint32_t b[4];
            LDSM4(b, kb + (uint32_t)(((16 * q + bRow) * 72 + ke * 16 + bCol) * 2));
            mma_f16(cS[2 * q],     a[0], a[1], a[2], a[3], b[0], b[1]);
            mma_f16(cS[2 * q + 1], a[0], a[1], a[2], a[3], b[2], b[3]);
        }
    }

#pragma unroll
    for (int hrow = 0; hrow < 2; hrow++) {
        int o = 2 * hrow;
        float mx = -1e30f;
#pragma unroll
        for (int nt = 0; nt < 8; nt++) {
#pragma unroll
            for (int e = 0; e < 2; e++) {
                int t = nt * 8 + c2 + e;
                float v = cS[nt][o + e] * 0.125f;
                if (scnt[t] <= n) v = -1e30f;
                cS[nt][o + e] = v;
                mx = fmaxf(mx, v);
            }
        }
        mx = fmaxf(mx, __shfl_xor_sync(0xffffffffu, mx, 1));
        mx = fmaxf(mx, __shfl_xor_sync(0xffffffffu, mx, 2));
        float sum = 0.f;
#pragma unroll
        for (int nt = 0; nt < 8; nt++) {
#pragma unroll
            for (int e = 0; e < 2; e++) {
                float p = __expf(cS[nt][o + e] - mx);
                cS[nt][o + e] = p;
                sum += p;
            }
        }
        sum += __shfl_xor_sync(0xffffffffu, sum, 1);
        sum += __shfl_xor_sync(0xffffffffu, sum, 2);
        float inv = 1.f / sum;
#pragma unroll
        for (int nt = 0; nt < 8; nt++) {
            cS[nt][o + 0] *= inv;
            cS[nt][o + 1] *= inv;
        }
    }

    uint32_t pa[4][4];
#pragma unroll
    for (int j = 0; j < 4; j++) {
        pa[j][0] = packh2(cS[2 * j][0],     cS[2 * j][1]);
        pa[j][1] = packh2(cS[2 * j][2],     cS[2 * j][3]);
        pa[j][2] = packh2(cS[2 * j + 1][0], cS[2 * j + 1][1]);
        pa[j][3] = packh2(cS[2 * j + 1][2], cS[2 * j + 1][3]);
    }

    float cO[8][4];
#pragma unroll
    for (int i = 0; i < 8; i++)
#pragma unroll
        for (int j = 0; j < 4; j++) cO[i][j] = 0.f;

#pragma unroll
    for (int j = 0; j < 4; j++) {
#pragma unroll
        for (int p = 0; p < 4; p++) {
            uint32_t b[4];
            LDSM4T(b, vbs + (uint32_t)(((16 * j + vRow) * 72 + p * 16 + vCol) * 2));
            mma_f16(cO[2 * p],     pa[j][0], pa[j][1], pa[j][2], pa[j][3], b[0], b[1]);
            mma_f16(cO[2 * p + 1], pa[j][0], pa[j][1], pa[j][2], pa[j][3], b[2], b[3]);
        }
    }

    int r = s0 + (lane >> 2);
#pragma unroll
    for (int nt = 0; nt < 8; nt++) {
        int col = h * 64 + nt * 8 + c2;
        uint32_t lo = packh2(cO[nt][0], cO[nt][1]);
        uint32_t hi = packh2(cO[nt][2], cO[nt][3]);
        *(uint32_t*)(ATT + (size_t)(n * 64 + r) * 512 + col)     = lo;
        *(uint32_t*)(ATT + (size_t)(n * 64 + r + 8) * 512 + col) = hi;
    }
}

// ---------------------------------------------------------------------------
// LayerNorm: fp16 in, fp16 out (fp32 stats)
// ---------------------------------------------------------------------------
__global__ void k_ln(const __half* __restrict__ in, const float* __restrict__ gam,
                     const float* __restrict__ bet, __half* __restrict__ outp) {
    int r = blockIdx.x;
    if (r >= g_maxn * 64) return;
    int t = threadIdx.x;
    const __half2* ip = (const __half2*)(in + (size_t)r * 512 + t * 4);
    float2 a = __half22float2(ip[0]);
    float2 b = __half22float2(ip[1]);
    float4 v = make_float4(a.x, a.y, b.x, b.y);
    float s  = v.x + v.y + v.z + v.w;
    float ss = fmaf(v.x, v.x, fmaf(v.y, v.y, fmaf(v.z, v.z, v.w * v.w)));
#pragma unroll
    for (int o = 16; o; o >>= 1) {
        s  += __shfl_xor_sync(0xffffffffu, s,  o);
        ss += __shfl_xor_sync(0xffffffffu, ss, o);
    }
    __shared__ float sh[8];
    if ((t & 31) == 0) { sh[t >> 5] = s; sh[4 + (t >> 5)] = ss; }
    __syncthreads();
    s  = sh[0] + sh[1] + sh[2] + sh[3];
    ss = sh[4] + sh[5] + sh[6] + sh[7];
    float mean = s * (1.f / 512.f);
    float var  = ss * (1.f / 512.f) - mean * mean;
    float inv  = rsqrtf(var + 1e-5f);
    float4 g4 = ((const float4*)gam)[t];
    float4 b4 = ((const float4*)bet)[t];
    float o0 = (v.x - mean) * inv * g4.x + b4.x;
    float o1 = (v.y - mean) * inv * g4.y + b4.y;
    float o2 = (v.z - mean) * inv * g4.z + b4.z;
    float o3 = (v.w - mean) * inv * g4.w + b4.w;
    __half2* d = (__half2*)(outp + (size_t)r * 512 + t * 4);
    d[0] = __floats2half2_rn(o0, o1);
    d[1] = __floats2half2_rn(o2, o3);
}

__global__ void k_pool(const __half* __restrict__ Xh, float* __restrict__ out) {
    int g = blockIdx.x;
    int d = threadIdx.x;
    int mx = g_maxn;
    const __half* p = Xh + (size_t)g * 512 + d;
    const size_t stride = 64 * 512;
    float s0 = 0.f, s1 = 0.f, s2 = 0.f, s3 = 0.f;
    int n = 0;
    for (; n + 4 <= mx; n += 4) {
        s0 += __half2float(p[(size_t)(n + 0) * stride]);
        s1 += __half2float(p[(size_t)(n + 1) * stride]);
        s2 += __half2float(p[(size_t)(n + 2) * stride]);
        s3 += __half2float(p[(size_t)(n + 3) * stride]);
    }
    for (; n < mx; n++) s0 += __half2float(p[(size_t)n * stride]);
    out[g * 512 + d] = (s0 + s1 + s2 + s3) / (float)mx;
}

// ---------------------------------------------------------------------------
// Launch
// ---------------------------------------------------------------------------
extern "C" void kernel_launch(void* const* d_in, const int* in_sizes, int n_in,
                              void* d_out, int out_size) {
    const float* emb  = (const float*)d_in[0];
    const int*   sidx = (const int*)  d_in[1];
    const float* W_in = (const float*)d_in[2];
    const float* b_in = (const float*)d_in[3];
    const float* W_o  = (const float*)d_in[4];
    const float* b_o  = (const float*)d_in[5];
    const float* ln1g = (const float*)d_in[6];
    const float* ln1b = (const float*)d_in[7];
    const float* W1   = (const float*)d_in[8];
    const float* b1   = (const float*)d_in[9];
    const float* W2   = (const float*)d_in[10];
    const float* b2   = (const float*)d_in[11];
    const float* ln2g = (const float*)d_in[12];
    const float* ln2b = (const float*)d_in[13];
    float* out = (float*)d_out;
    (void)n_in; (void)out_size;

    int N = in_sizes[0] / 512;

    __half *pXh, *pQKVh, *pATTh, *pTMPh, *pY1h, *pHIDh, *pWh;
    cudaGetSymbolAddress((void**)&pXh,   g_Xh);
    cudaGetSymbolAddress((void**)&pQKVh, g_QKVh);
    cudaGetSymbolAddress((void**)&pATTh, g_ATTh);
    cudaGetSymbolAddress((void**)&pTMPh, g_TMPh);
    cudaGetSymbolAddress((void**)&pY1h,  g_Y1h);
    cudaGetSymbolAddress((void**)&pHIDh, g_HIDh);
    cudaGetSymbolAddress((void**)&pWh,   g_Wh);

    __half* hWin = pWh;
    __half* hWo  = pWh + 786432;
    __half* hW1  = pWh + 1048576;
    __half* hW2  = pWh + 1572864;

    cudaFuncSetAttribute(k_tgemm, cudaFuncAttributeMaxDynamicSharedMemorySize,
                         (int)TG_SMEM_BYTES);

    const int GY = ROWS_CAP / 128;

    k_meta<<<1, 128>>>(sidx, N);
    k_zeropad<<<64, 256>>>();
    k_scatter<<<N, 128>>>(emb, sidx);
    k_cvtw<<<768, 256>>>(W_in, hWin, 196608);
    k_cvtw<<<256, 256>>>(W_o,  hWo,   65536);
    k_cvtw<<<512, 256>>>(W1,   hW1,  131072);
    k_cvtw<<<512, 256>>>(W2,   hW2,  131072);

    // QKV = X @ W_in^T + b_in                      [M, 1536] fp16
    k_tgemm<<<dim3(12, GY), 256, TG_SMEM_BYTES>>>(pXh, hWin, b_in, nullptr,
                                                  pQKVh, 1536, 512, 0);

    // tensor-core attention                         -> ATT [M, 512] fp16
    k_attn<<<dim3(CAP, 8), 128>>>(pQKVh, pATTh);

    // TMP = ATT @ W_o^T + b_o + X                  [M, 512] fp16
    k_tgemm<<<dim3(4, GY), 256, TG_SMEM_BYTES>>>(pATTh, hWo, b_o, pXh,
                                                 pTMPh, 512, 512, 0);

    // Y1 = LN1(TMP) -> fp16
    k_ln<<<ROWS_CAP, 128>>>(pTMPh, ln1g, ln1b, pY1h);

    // HID = relu(Y1 @ W1^T + b1)                   [M, 1024] fp16
    k_tgemm<<<dim3(8, GY), 256, TG_SMEM_BYTES>>>(pY1h, hW1, b1, nullptr,
                                                 pHIDh, 1024, 512, 1);

    // TMP = HID @ W2^T + b2 + Y1                   [M, 512] fp16
    k_tgemm<<<dim3(4, GY), 256, TG_SMEM_BYTES>>>(pHIDh, hW2, b2, pY1h,
                                                 pTMPh, 512, 1024, 0);

    // X2 = LN2(TMP) -> fp16 in place
    k_ln<<<ROWS_CAP, 128>>>(pTMPh, ln2g, ln2b, pTMPh);

    k_pool<<<64, 512>>>(pTMPh, out);
}

// round 13
// speedup vs baseline: 4.0813x; 1.0167x over previous
#include <cuda_runtime.h>
#include <cuda_fp16.h>
#include <math.h>
#include <stdint.h>

// ---------------------------------------------------------------------------
// Problem: D=512, H=8 (e=64), B=64 studies, N=131072 cells.
// Padded layout: row r = n*64 + g. max_n data-dependent; CAP upper bound.
// fp16 datapath everywhere except LN stats / softmax / pool accumulation.
// ---------------------------------------------------------------------------
#define CAP       2560
#define ROWS_CAP  (CAP * 64)   // 163840

__device__ int g_maxn;
__device__ int g_starts[65];
__device__ int g_counts[64];

__device__ __align__(128) __half g_Xh  [(size_t)ROWS_CAP * 512];
__device__ __align__(128) __half g_QKVh[(size_t)ROWS_CAP * 1536];
__device__ __align__(128) __half g_ATTh[(size_t)ROWS_CAP * 512];
__device__ __align__(128) __half g_TMPh[(size_t)ROWS_CAP * 512];
__device__ __align__(128) __half g_Y1h [(size_t)ROWS_CAP * 512];
__device__ __align__(128) __half g_HIDh[(size_t)ROWS_CAP * 1024];
__device__ __align__(128) __half g_Wh  [2097152];  // fp16 W_in | W_o | W1 | W2
__device__ float g_PART[16 * 64 * 512];            // pool partials

// ---------------------------------------------------------------------------
// Meta / zeropad / scatter / weight conversion
// ---------------------------------------------------------------------------
__global__ void k_meta(const int* __restrict__ idx, int N) {
    __shared__ int st[65];
    __shared__ int smax;
    int t = threadIdx.x;
    if (t == 0) smax = 0;
    if (t <= 64) {
        if (t == 64) st[64] = N;
        else {
            int lo = 0, hi = N;
            while (lo < hi) { int mid = (lo + hi) >> 1; if (idx[mid] < t) lo = mid + 1; else hi = mid; }
            st[t] = lo;
        }
    }
    __syncthreads();
    if (t < 64) {
        int c = st[t + 1] - st[t];
        g_starts[t] = st[t];
        g_counts[t] = c;
        atomicMax(&smax, c);
    }
    if (t == 64) g_starts[64] = N;
    __syncthreads();
    if (t == 0) g_maxn = (smax < CAP) ? smax : CAP;
}

__global__ void k_zeropad() {
    int g = blockIdx.x;
    int c0 = g_counts[g];
    int rows = g_maxn - c0;
    if (rows <= 0) return;
    uint4 z = make_uint4(0u, 0u, 0u, 0u);
    for (int w = threadIdx.x; w < rows * 64; w += 256) {
        int n = c0 + (w >> 6);
        int j = w & 63;
        ((uint4*)(g_Xh + (size_t)((n << 6) + g) * 512))[j] = z;
    }
}

__global__ void k_scatter(const float* __restrict__ emb, const int* __restrict__ idx) {
    int i = blockIdx.x;
    int g = idx[i];
    int n = i - g_starts[g];
    int t = threadIdx.x;
    float4 v = ((const float4*)(emb + (size_t)i * 512))[t];
    __half2* d = (__half2*)(g_Xh + (size_t)(n * 64 + g) * 512 + t * 4);
    d[0] = __floats2half2_rn(v.x, v.y);
    d[1] = __floats2half2_rn(v.z, v.w);
}

__global__ void k_cvtwA(const float* __restrict__ s, __half* __restrict__ d, int n4) {
    int i = blockIdx.x * 256 + threadIdx.x;
    if (i >= n4) return;
    float4 v = ((const float4*)s)[i];
    __half2* p = (__half2*)(d + (size_t)i * 4);
    p[0] = __floats2half2_rn(v.x, v.y);
    p[1] = __floats2half2_rn(v.z, v.w);
}

// W_o (65536 f4) | W1 (131072 f4) | W2 (131072 f4) -> g_Wh + 786432 halves
__global__ void k_cvtwB(const float* __restrict__ wo, const float* __restrict__ w1,
                        const float* __restrict__ w2, __half* __restrict__ d) {
    int i = blockIdx.x * 256 + threadIdx.x;
    if (i >= 327680) return;
    const float4* src;
    if (i < 65536)       src = (const float4*)wo + i;
    else if (i < 196608) src = (const float4*)w1 + (i - 65536);
    else                 src = (const float4*)w2 + (i - 196608);
    float4 v = *src;
    __half2* p = (__half2*)(d + (size_t)i * 4);
    p[0] = __floats2half2_rn(v.x, v.y);
    p[1] = __floats2half2_rn(v.z, v.w);
}

// ---------------------------------------------------------------------------
// fp16 mma helpers
// ---------------------------------------------------------------------------
__device__ __forceinline__ void mma_f16(float c[4],
                                        uint32_t a0, uint32_t a1, uint32_t a2, uint32_t a3,
                                        uint32_t b0, uint32_t b1) {
    asm volatile(
        "mma.sync.aligned.m16n8k16.row.col.f32.f16.f16.f32 "
        "{%0,%1,%2,%3}, {%4,%5,%6,%7}, {%8,%9}, {%0,%1,%2,%3};"
        : "+f"(c[0]), "+f"(c[1]), "+f"(c[2]), "+f"(c[3])
        : "r"(a0), "r"(a1), "r"(a2), "r"(a3), "r"(b0), "r"(b1));
}
#define LDSM4(f, a) \
    asm volatile("ldmatrix.sync.aligned.m8n8.x4.shared.b16 {%0,%1,%2,%3}, [%4];" \
                 : "=r"((f)[0]), "=r"((f)[1]), "=r"((f)[2]), "=r"((f)[3]) : "r"(a))
#define LDSM4T(f, a) \
    asm volatile("ldmatrix.sync.aligned.m8n8.x4.trans.shared.b16 {%0,%1,%2,%3}, [%4];" \
                 : "=r"((f)[0]), "=r"((f)[1]), "=r"((f)[2]), "=r"((f)[3]) : "r"(a))

__device__ __forceinline__ uint32_t packh2(float a, float b) {
    __half2 h = __floats2half2_rn(a, b);
    return *(uint32_t*)&h;
}

// ---------------------------------------------------------------------------
// fp16 tensor-core GEMM (proven R12): C = A*Bw^T + bias (+resid)(relu), fp16.
// BM=BN=128, BK=64 halves; 8 warps, warp tile 64x32; 3-stage cp.async ring.
// ---------------------------------------------------------------------------
#define SROW_H 72
#define A_BYTES (128u * SROW_H * 2u)    // 18432
#define STAGE_B (2u * A_BYTES)          // 36864
#define TG_SMEM_BYTES (3u * STAGE_B)    // 110592

__global__ __launch_bounds__(256, 2)
void k_tgemm(const __half* __restrict__ A, const __half* __restrict__ Bw,
             const float* __restrict__ bias, const __half* __restrict__ resid,
             __half* __restrict__ C, int Ncols, int K, int relu)
{
    int M = g_maxn * 64;
    int row0 = blockIdx.y * 128;
    if (row0 >= M) return;
    int col0 = blockIdx.x * 128;

    int tid  = threadIdx.x;
    int lane = tid & 31;
    int wid  = tid >> 5;
    int wm   = wid & 1;
    int wn   = wid >> 1;
    int g    = lane >> 2;
    int tg   = lane & 3;

    extern __shared__ uint32_t sm[];
    uint32_t smb = (uint32_t)__cvta_generic_to_shared(sm);

    const __half* Abase = A  + (size_t)row0 * K;
    const __half* Bbase = Bw + (size_t)col0 * K;

    int srow = tid >> 3;
    int sc8  = tid & 7;

    uint32_t rowA = (uint32_t)((wm * 64 + (lane & 15)) * SROW_H * 2);
    uint32_t kA   = (uint32_t)((lane >> 4) * 16);
    uint32_t rowB = (uint32_t)((wn * 32 + (lane & 7) + ((lane >> 3) & 1) * 8) * SROW_H * 2);
    uint32_t kB   = (uint32_t)((lane >> 4) * 16);

    float c[4][4][4];
#pragma unroll
    for (int i = 0; i < 4; i++)
#pragma unroll
        for (int j = 0; j < 4; j++)
#pragma unroll
            for (int k = 0; k < 4; k++) c[i][j][k] = 0.f;

    const int KT = K >> 6;

#define STAGE(kt_)  do {                                                          \
        int _kt = (kt_);                                                          \
        uint32_t _sb = smb + (uint32_t)(_kt % 3) * STAGE_B;                       \
        int _ko = _kt * 64 + sc8 * 8;                                             \
        _Pragma("unroll")                                                         \
        for (int _i = 0; _i < 4; _i++) {                                          \
            int _row = srow + 32 * _i;                                            \
            uint32_t _d = _sb + (uint32_t)((_row * SROW_H + sc8 * 8) * 2);        \
            int _ok = (row0 + _row) < M;                                          \
            const __half* _sa = Abase + (size_t)(_ok ? _row : 0) * K + _ko;       \
            int _sz = _ok ? 16 : 0;                                               \
            asm volatile("cp.async.cg.shared.global [%0], [%1], 16, %2;"          \
                         :: "r"(_d), "l"(_sa), "r"(_sz));                         \
            uint32_t _d2 = _d + A_BYTES;                                          \
            const __half* _sb2 = Bbase + (size_t)_row * K + _ko;                  \
            asm volatile("cp.async.cg.shared.global [%0], [%1], 16;"              \
                         :: "r"(_d2), "l"(_sb2));                                 \
        }                                                                         \
        asm volatile("cp.async.commit_group;");                                   \
    } while (0)

    STAGE(0);
    STAGE(1);

    uint32_t fa[2][4][4], fb[2][2][4];

    for (int kt = 0; kt < KT; kt++) {
        if (kt + 1 < KT) { asm volatile("cp.async.wait_group 1;"); }
        else             { asm volatile("cp.async.wait_group 0;"); }
        __syncthreads();
        if (kt + 2 < KT) STAGE(kt + 2);

        uint32_t aB = smb + (uint32_t)(kt % 3) * STAGE_B;
        uint32_t bB = aB + A_BYTES;

#pragma unroll
        for (int mt = 0; mt < 4; mt++)
            LDSM4(fa[0][mt], aB + rowA + (uint32_t)(mt * 16 * SROW_H * 2) + kA);
#pragma unroll
        for (int p = 0; p < 2; p++)
            LDSM4(fb[0][p], bB + rowB + (uint32_t)(p * 16 * SROW_H * 2) + kB);

#pragma unroll
        for (int kk = 0; kk < 4; kk++) {
            const int cb = kk & 1, nb = cb ^ 1;
            if (kk < 3) {
                uint32_t ko = (uint32_t)((kk + 1) * 32);
#pragma unroll
                for (int mt = 0; mt < 4; mt++)
                    LDSM4(fa[nb][mt], aB + rowA + (uint32_t)(mt * 16 * SROW_H * 2) + kA + ko);
#pragma unroll
                for (int p = 0; p < 2; p++)
                    LDSM4(fb[nb][p], bB + rowB + (uint32_t)(p * 16 * SROW_H * 2) + kB + ko);
            }
#pragma unroll
            for (int p = 0; p < 2; p++)
#pragma unroll
                for (int mt = 0; mt < 4; mt++) {
                    mma_f16(c[mt][2 * p],
                            fa[cb][mt][0], fa[cb][mt][1], fa[cb][mt][2], fa[cb][mt][3],
                            fb[cb][p][0], fb[cb][p][2]);
                    mma_f16(c[mt][2 * p + 1],
                            fa[cb][mt][0], fa[cb][mt][1], fa[cb][mt][2], fa[cb][mt][3],
                            fb[cb][p][1], fb[cb][p][3]);
                }
        }
    }

#pragma unroll
    for (int mt = 0; mt < 4; mt++) {
        int r0 = row0 + wm * 64 + mt * 16 + g;
        int r1 = r0 + 8;
#pragma unroll
        for (int nt = 0; nt < 4; nt++) {
            int cc = col0 + wn * 32 + nt * 8 + 2 * tg;
            float2 bv = *(const float2*)(bias + cc);
#pragma unroll
            for (int hrow = 0; hrow < 2; hrow++) {
                int r = hrow ? r1 : r0;
                if (r >= M) continue;
                float o0 = c[mt][nt][2 * hrow + 0] + bv.x;
                float o1 = c[mt][nt][2 * hrow + 1] + bv.y;
                if (resid) {
                    __half2 rv = *(const __half2*)(resid + (size_t)r * Ncols + cc);
                    float2 rf = __half22float2(rv);
                    o0 += rf.x; o1 += rf.y;
                }
                if (relu) { o0 = fmaxf(o0, 0.f); o1 = fmaxf(o1, 0.f); }
                *(__half2*)(C + (size_t)r * Ncols + cc) = __floats2half2_rn(o0, o1);
            }
        }
    }
#undef STAGE
}

// ---------------------------------------------------------------------------
// Tensor-core attention (proven R11): one block (128 thr) per (n, h).
// ---------------------------------------------------------------------------
__global__ __launch_bounds__(128)
void k_attn(const __half* __restrict__ QKVh, __half* __restrict__ ATT) {
    int n = blockIdx.x;
    if (n >= g_maxn) return;
    int h = blockIdx.y;

    __shared__ __half sQ[64 * 72];
    __shared__ __half sK[64 * 72];
    __shared__ __half sV[64 * 72];
    __shared__ int scnt[64];

    int tid  = threadIdx.x;
    int lane = tid & 31;
    int w    = tid >> 5;

    if (tid < 64) scnt[tid] = g_counts[tid];

    const __half* base = QKVh + (size_t)n * 64 * 1536 + (size_t)h * 64;
    for (int i = tid; i < 1536; i += 128) {
        int m   = i >> 9;
        int rem = i & 511;
        int row = rem >> 3;
        int c8  = rem & 7;
        const uint4* src = (const uint4*)(base + (size_t)row * 1536 + m * 512 + c8 * 8);
        __half* dstm = (m == 0) ? sQ : ((m == 1) ? sK : sV);
        *(uint4*)(dstm + row * 72 + c8 * 8) = *src;
    }
    __syncthreads();

    uint32_t qb  = (uint32_t)__cvta_generic_to_shared(sQ);
    uint32_t kb  = (uint32_t)__cvta_generic_to_shared(sK);
    uint32_t vbs = (uint32_t)__cvta_generic_to_shared(sV);

    int s0 = w * 16;
    int c2 = 2 * (lane & 3);

    int aRow = s0 + (lane & 7) + ((lane & 8) ? 8 : 0);
    int aCol = ((lane & 16) ? 8 : 0);
    int bRow = (lane & 7) + ((lane & 16) ? 8 : 0);
    int bCol = ((lane & 8) ? 8 : 0);
    int vRow = (lane & 7) + ((lane & 8) ? 8 : 0);
    int vCol = ((lane & 16) ? 8 : 0);

    float cS[8][4];
#pragma unroll
    for (int i = 0; i < 8; i++)
#pragma unroll
        for (int j = 0; j < 4; j++) cS[i][j] = 0.f;

#pragma unroll
    for (int ke = 0; ke < 4; ke++) {
        uint32_t a[4];
        LDSM4(a, qb + (uint32_t)((aRow * 72 + ke * 16 + aCol) * 2));
#pragma unroll
        for (int q = 0; q < 4; q++) {
            uint32_t b[4];
            LDSM4(b, kb + (uint32_t)(((16 * q + bRow) * 72 + ke * 16 + bCol) * 2));
            mma_f16(cS[2 * q],     a[0], a[1], a[2], a[3], b[0], b[1]);
            mma_f16(cS[2 * q + 1], a[0], a[1], a[2], a[3], b[2], b[3]);
        }
    }

#pragma unroll
    for (int hrow = 0; hrow < 2; hrow++) {
        int o = 2 * hrow;
        float mx = -1e30f;
#pragma unroll
        for (int nt = 0; nt < 8; nt++) {
#pragma unroll
            for (int e = 0; e < 2; e++) {
                int t = nt * 8 + c2 + e;
                float v = cS[nt][o + e] * 0.125f;
                if (scnt[t] <= n) v = -1e30f;
                cS[nt][o + e] = v;
                mx = fmaxf(mx, v);
            }
        }
        mx = fmaxf(mx, __shfl_xor_sync(0xffffffffu, mx, 1));
        mx = fmaxf(mx, __shfl_xor_sync(0xffffffffu, mx, 2));
        float sum = 0.f;
#pragma unroll
        for (int nt = 0; nt < 8; nt++) {
#pragma unroll
            for (int e = 0; e < 2; e++) {
                float p = __expf(cS[nt][o + e] - mx);
                cS[nt][o + e] = p;
                sum += p;
            }
        }
        sum += __shfl_xor_sync(0xffffffffu, sum, 1);
        sum += __shfl_xor_sync(0xffffffffu, sum, 2);
        float inv = 1.f / sum;
#pragma unroll
        for (int nt = 0; nt < 8; nt++) {
            cS[nt][o + 0] *= inv;
            cS[nt][o + 1] *= inv;
        }
    }

    uint32_t pa[4][4];
#pragma unroll
    for (int j = 0; j < 4; j++) {
        pa[j][0] = packh2(cS[2 * j][0],     cS[2 * j][1]);
        pa[j][1] = packh2(cS[2 * j][2],     cS[2 * j][3]);
        pa[j][2] = packh2(cS[2 * j + 1][0], cS[2 * j + 1][1]);
        pa[j][3] = packh2(cS[2 * j + 1][2], cS[2 * j + 1][3]);
    }

    float cO[8][4];
#pragma unroll
    for (int i = 0; i < 8; i++)
#pragma unroll
        for (int j = 0; j < 4; j++) cO[i][j] = 0.f;

#pragma unroll
    for (int j = 0; j < 4; j++) {
#pragma unroll
        for (int p = 0; p < 4; p++) {
            uint32_t b[4];
            LDSM4T(b, vbs + (uint32_t)(((16 * j + vRow) * 72 + p * 16 + vCol) * 2));
            mma_f16(cO[2 * p],     pa[j][0], pa[j][1], pa[j][2], pa[j][3], b[0], b[1]);
            mma_f16(cO[2 * p + 1], pa[j][0], pa[j][1], pa[j][2], pa[j][3], b[2], b[3]);
        }
    }

    int r = s0 + (lane >> 2);
#pragma unroll
    for (int nt = 0; nt < 8; nt++) {
        int col = h * 64 + nt * 8 + c2;
        uint32_t lo = packh2(cO[nt][0], cO[nt][1]);
        uint32_t hi = packh2(cO[nt][2], cO[nt][3]);
        *(uint32_t*)(ATT + (size_t)(n * 64 + r) * 512 + col)     = lo;
        *(uint32_t*)(ATT + (size_t)(n * 64 + r + 8) * 512 + col) = hi;
    }
}

// ---------------------------------------------------------------------------
// LayerNorm (LN1): fp16 in, fp16 out (fp32 stats)
// ---------------------------------------------------------------------------
__global__ void k_ln(const __half* __restrict__ in, const float* __restrict__ gam,
                     const float* __restrict__ bet, __half* __restrict__ outp) {
    int r = blockIdx.x;
    if (r >= g_maxn * 64) return;
    int t = threadIdx.x;
    const __half2* ip = (const __half2*)(in + (size_t)r * 512 + t * 4);
    float2 a = __half22float2(ip[0]);
    float2 b = __half22float2(ip[1]);
    float4 v = make_float4(a.x, a.y, b.x, b.y);
    float s  = v.x + v.y + v.z + v.w;
    float ss = fmaf(v.x, v.x, fmaf(v.y, v.y, fmaf(v.z, v.z, v.w * v.w)));
#pragma unroll
    for (int o = 16; o; o >>= 1) {
        s  += __shfl_xor_sync(0xffffffffu, s,  o);
        ss += __shfl_xor_sync(0xffffffffu, ss, o);
    }
    __shared__ float sh[8];
    if ((t & 31) == 0) { sh[t >> 5] = s; sh[4 + (t >> 5)] = ss; }
    __syncthreads();
    s  = sh[0] + sh[1] + sh[2] + sh[3];
    ss = sh[4] + sh[5] + sh[6] + sh[7];
    float mean = s * (1.f / 512.f);
    float var  = ss * (1.f / 512.f) - mean * mean;
    float inv  = rsqrtf(var + 1e-5f);
    float4 g4 = ((const float4*)gam)[t];
    float4 b4 = ((const float4*)bet)[t];
    float o0 = (v.x - mean) * inv * g4.x + b4.x;
    float o1 = (v.y - mean) * inv * g4.y + b4.y;
    float o2 = (v.z - mean) * inv * g4.z + b4.z;
    float o3 = (v.w - mean) * inv * g4.w + b4.w;
    __half2* d = (__half2*)(outp + (size_t)r * 512 + t * 4);
    d[0] = __floats2half2_rn(o0, o1);
    d[1] = __floats2half2_rn(o2, o3);
}

// ---------------------------------------------------------------------------
// Fused LN2 + pool partials: block (chunk, g) normalizes its rows and
// accumulates per-column sums into g_PART[chunk][g][d]. 512 threads.
// ---------------------------------------------------------------------------
__global__ __launch_bounds__(512)
void k_lnpool(const __half* __restrict__ in, const float* __restrict__ gam,
              const float* __restrict__ bet, float* __restrict__ part) {
    int chunk = blockIdx.x;    // 0..15
    int g     = blockIdx.y;    // 0..63
    int d     = threadIdx.x;   // 0..511
    int wid = d >> 5, lane = d & 31;

    int mx = g_maxn;
    int CH = (mx + 15) >> 4;
    int n0 = chunk * CH;
    int n1 = n0 + CH; if (n1 > mx) n1 = mx;

    __shared__ float shS[16], shQ[16], bc[2];
    float gd = gam[d], bd = bet[d];
    float acc = 0.f;

    if (n0 < n1) {
        float v = __half2float(in[(size_t)(n0 * 64 + g) * 512 + d]);
        for (int n = n0; n < n1; n++) {
            float vn = 0.f;
            if (n + 1 < n1)
                vn = __half2float(in[(size_t)((n + 1) * 64 + g) * 512 + d]);
            float s = v, ss = v * v;
#pragma unroll
            for (int o = 16; o; o >>= 1) {
                s  += __shfl_xor_sync(0xffffffffu, s,  o);
                ss += __shfl_xor_sync(0xffffffffu, ss, o);
            }
            if (lane == 0) { shS[wid] = s; shQ[wid] = ss; }
            __syncthreads();
            if (wid == 0) {
                float s2 = (lane < 16) ? shS[lane] : 0.f;
                float q2 = (lane < 16) ? shQ[lane] : 0.f;
#pragma unroll
                for (int o = 8; o; o >>= 1) {
                    s2 += __shfl_xor_sync(0xffffffffu, s2, o);
                    q2 += __shfl_xor_sync(0xffffffffu, q2, o);
                }
                if (lane == 0) { bc[0] = s2; bc[1] = q2; }
            }
            __syncthreads();
            float mean = bc[0] * (1.f / 512.f);
            float var  = bc[1] * (1.f / 512.f) - mean * mean;
            float inv  = rsqrtf(var + 1e-5f);
            acc += (v - mean) * inv * gd + bd;
            v = vn;
        }
    }
    part[(size_t)(chunk * 64 + g) * 512 + d] = acc;
}

// deterministic reduction of the 16 chunk partials + mean division
__global__ void k_poolred(const float* __restrict__ part, float* __restrict__ out) {
    int g = blockIdx.x;
    int d = threadIdx.x;
    float s = 0.f;
#pragma unroll
    for (int c = 0; c < 16; c++)
        s += part[(size_t)(c * 64 + g) * 512 + d];
    out[g * 512 + d] = s / (float)g_maxn;
}

// ---------------------------------------------------------------------------
// Launch
// ---------------------------------------------------------------------------
extern "C" void kernel_launch(void* const* d_in, const int* in_sizes, int n_in,
                              void* d_out, int out_size) {
    const float* emb  = (const float*)d_in[0];
    const int*   sidx = (const int*)  d_in[1];
    const float* W_in = (const float*)d_in[2];
    const float* b_in = (const float*)d_in[3];
    const float* W_o  = (const float*)d_in[4];
    const float* b_o  = (const float*)d_in[5];
    const float* ln1g = (const float*)d_in[6];
    const float* ln1b = (const float*)d_in[7];
    const float* W1   = (const float*)d_in[8];
    const float* b1   = (const float*)d_in[9];
    const float* W2   = (const float*)d_in[10];
    const float* b2   = (const float*)d_in[11];
    const float* ln2g = (const float*)d_in[12];
    const float* ln2b = (const float*)d_in[13];
    float* out = (float*)d_out;
    (void)n_in; (void)out_size;

    int N = in_sizes[0] / 512;

    __half *pXh, *pQKVh, *pATTh, *pTMPh, *pY1h, *pHIDh, *pWh;
    float *pPART;
    cudaGetSymbolAddress((void**)&pXh,   g_Xh);
    cudaGetSymbolAddress((void**)&pQKVh, g_QKVh);
    cudaGetSymbolAddress((void**)&pATTh, g_ATTh);
    cudaGetSymbolAddress((void**)&pTMPh, g_TMPh);
    cudaGetSymbolAddress((void**)&pY1h,  g_Y1h);
    cudaGetSymbolAddress((void**)&pHIDh, g_HIDh);
    cudaGetSymbolAddress((void**)&pWh,   g_Wh);
    cudaGetSymbolAddress((void**)&pPART, g_PART);

    __half* hWin = pWh;
    __half* hWo  = pWh + 786432;

    cudaFuncSetAttribute(k_tgemm, cudaFuncAttributeMaxDynamicSharedMemorySize,
                         (int)TG_SMEM_BYTES);

    const int GY = ROWS_CAP / 128;

    k_meta<<<1, 128>>>(sidx, N);                                    // #1
    k_zeropad<<<64, 256>>>();                                       // #2
    k_scatter<<<N, 128>>>(emb, sidx);                               // #3
    k_cvtwA<<<768, 256>>>(W_in, hWin, 196608);                      // #4
    k_cvtwB<<<1280, 256>>>(W_o, W1, W2, hWo);                       // #5

    // QKV = X @ W_in^T + b_in                      [M, 1536]      // #6 (ncu)
    k_tgemm<<<dim3(12, GY), 256, TG_SMEM_BYTES>>>(pXh, hWin, b_in, nullptr,
                                                  pQKVh, 1536, 512, 0);

    // tensor-core attention                         -> ATT fp16
    k_attn<<<dim3(CAP, 8), 128>>>(pQKVh, pATTh);

    // TMP = ATT @ W_o^T + b_o + X                  [M, 512]
    k_tgemm<<<dim3(4, GY), 256, TG_SMEM_BYTES>>>(pATTh, hWo, b_o, pXh,
                                                 pTMPh, 512, 512, 0);

    // Y1 = LN1(TMP)
    k_ln<<<ROWS_CAP, 128>>>(pTMPh, ln1g, ln1b, pY1h);

    // HID = relu(Y1 @ W1^T + b1)                   [M, 1024]
    k_tgemm<<<dim3(8, GY), 256, TG_SMEM_BYTES>>>(pY1h, pWh + 1048576, b1, nullptr,
                                                 pHIDh, 1024, 512, 1);

    // TMP = HID @ W2^T + b2 + Y1                   [M, 512]
    k_tgemm<<<dim3(4, GY), 256, TG_SMEM_BYTES>>>(pHIDh, pWh + 1572864, b2, pY1h,
                                                 pTMPh, 512, 1024, 0);

    // fused LN2 + pool partials, then deterministic reduce
    k_lnpool<<<dim3(16, 64), 512>>>(pTMPh, ln2g, ln2b, pPART);
    k_poolred<<<64, 512>>>(pPART, out);
}